// round 1
// baseline (speedup 1.0000x reference)
#include <cuda_runtime.h>
#include <cuda_bf16.h>
#include <math.h>

#define N_NODES 100000
#define N_EDGES 1600000
#define F_IN 256
#define F_HID 128
#define VOCAB 100000
#define N_SAMP 512

// ---------------- scratch (static __device__ — no allocations) ----------------
__device__ float g_h[(size_t)N_NODES * F_HID];     // 51.2 MB, fits L2
__device__ float g_es1[N_NODES];
__device__ float g_ed1[N_NODES];
__device__ int   g_counts[N_NODES];
__device__ int   g_off[N_NODES + 1];
__device__ int   g_cursor[N_NODES];
__device__ int   g_csr_src[N_EDGES];
__device__ float g_h2[2 * N_NODES];
__device__ float g_es2[N_NODES];
__device__ float g_ed2[N_NODES];

// ---------------- CSR build ----------------
__global__ void zero_counts_k() {
    int i = blockIdx.x * blockDim.x + threadIdx.x;
    if (i < N_NODES) g_counts[i] = 0;
}

__global__ void hist_k(const int* __restrict__ edge_index) {
    int e = blockIdx.x * blockDim.x + threadIdx.x;
    if (e < N_EDGES) {
        int dst = edge_index[N_EDGES + e];
        atomicAdd(&g_counts[dst], 1);
    }
}

__global__ void scan_k() {
    __shared__ int s[1024];
    const int T = 1024;
    const int CH = (N_NODES + T - 1) / T;  // 98
    int t = threadIdx.x;
    int base = t * CH;
    int sum = 0;
    for (int i = 0; i < CH; i++) {
        int x = base + i;
        if (x < N_NODES) sum += g_counts[x];
    }
    s[t] = sum;
    __syncthreads();
    for (int d = 1; d < T; d <<= 1) {
        int v = 0;
        if (t >= d) v = s[t - d];
        __syncthreads();
        s[t] += v;
        __syncthreads();
    }
    int run = (t > 0) ? s[t - 1] : 0;
    for (int i = 0; i < CH; i++) {
        int x = base + i;
        if (x < N_NODES) {
            g_off[x] = run;
            g_cursor[x] = run;
            run += g_counts[x];
        }
    }
    if (t == T - 1) g_off[N_NODES] = run;
}

__global__ void fill_k(const int* __restrict__ edge_index) {
    int e = blockIdx.x * blockDim.x + threadIdx.x;
    if (e < N_EDGES) {
        int src = edge_index[e];
        int dst = edge_index[N_EDGES + e];
        int pos = atomicAdd(&g_cursor[dst], 1);
        g_csr_src[pos] = src;
    }
}

// ---------------- GEMM: h = X @ W1   [100000,256]x[256,128] fp32 ----------------
#define BM 64
#define BN 128
#define BK 16
__global__ __launch_bounds__(256) void gemm_k(const float* __restrict__ A,
                                              const float* __restrict__ B) {
    __shared__ float As[BM][BK + 1];
    __shared__ float Bs[BK][BN];
    int tid = threadIdx.x;
    int block_row = blockIdx.x * BM;
    int tr = tid >> 4;   // 0..15
    int tc = tid & 15;   // 0..15
    float acc[4][8];
#pragma unroll
    for (int i = 0; i < 4; i++)
#pragma unroll
        for (int j = 0; j < 8; j++) acc[i][j] = 0.f;

    for (int k0 = 0; k0 < F_IN; k0 += BK) {
        // load A tile: one float4 per thread
        {
            int r = tid >> 2;
            int c = (tid & 3) * 4;
            int gr = block_row + r;
            float4 av = make_float4(0.f, 0.f, 0.f, 0.f);
            if (gr < N_NODES) av = *(const float4*)(A + (size_t)gr * F_IN + k0 + c);
            As[r][c] = av.x; As[r][c + 1] = av.y; As[r][c + 2] = av.z; As[r][c + 3] = av.w;
        }
        // load B tile: two float4 per thread
#pragma unroll
        for (int i = 0; i < 2; i++) {
            int idx = tid * 2 + i;
            int kk = idx >> 5;
            int n4 = (idx & 31) * 4;
            float4 bv = *(const float4*)(B + (size_t)(k0 + kk) * F_HID + n4);
            *(float4*)(&Bs[kk][n4]) = bv;
        }
        __syncthreads();
#pragma unroll
        for (int kk = 0; kk < BK; kk++) {
            float a[4], b[8];
#pragma unroll
            for (int i = 0; i < 4; i++) a[i] = As[tr * 4 + i][kk];
#pragma unroll
            for (int j = 0; j < 8; j++) b[j] = Bs[kk][tc * 8 + j];
#pragma unroll
            for (int i = 0; i < 4; i++)
#pragma unroll
                for (int j = 0; j < 8; j++) acc[i][j] += a[i] * b[j];
        }
        __syncthreads();
    }
#pragma unroll
    for (int i = 0; i < 4; i++) {
        int gr = block_row + tr * 4 + i;
        if (gr < N_NODES) {
            float* cp = g_h + (size_t)gr * F_HID + tc * 8;
            *(float4*)cp = make_float4(acc[i][0], acc[i][1], acc[i][2], acc[i][3]);
            *(float4*)(cp + 4) = make_float4(acc[i][4], acc[i][5], acc[i][6], acc[i][7]);
        }
    }
}

// ---------------- attention dots: e_src/e_dst per node ----------------
__global__ void dots_k(const float* __restrict__ a_src, const float* __restrict__ a_dst) {
    int warp = (blockIdx.x * blockDim.x + threadIdx.x) >> 5;
    int lane = threadIdx.x & 31;
    if (warp >= N_NODES) return;
    const float* hp = g_h + (size_t)warp * F_HID;
    float es = 0.f, ed = 0.f;
#pragma unroll
    for (int k = 0; k < 4; k++) {
        int f = lane + 32 * k;
        float hv = hp[f];
        es += hv * a_src[f];
        ed += hv * a_dst[f];
    }
#pragma unroll
    for (int o = 16; o; o >>= 1) {
        es += __shfl_xor_sync(0xffffffffu, es, o);
        ed += __shfl_xor_sync(0xffffffffu, ed, o);
    }
    if (lane == 0) {
        g_es1[warp] = es;
        g_ed1[warp] = ed;
    }
}

__device__ __forceinline__ float leaky(float x) { return x > 0.f ? x : 0.2f * x; }

// ---------------- layer-1 aggregation + fused h2/e2 epilogue ----------------
__global__ __launch_bounds__(256) void agg1_k(const float* __restrict__ Wmu,
                                              const float* __restrict__ amus,
                                              const float* __restrict__ amud) {
    int warp = (blockIdx.x * blockDim.x + threadIdx.x) >> 5;
    int lane = threadIdx.x & 31;
    if (warp >= N_NODES) return;
    int v = warp;
    int beg = g_off[v], end = g_off[v + 1];
    float h2_0 = 0.f, h2_1 = 0.f;
    if (beg < end) {
        float edv = g_ed1[v];
        // pass 1: segment max (lanes parallel over edges)
        float m = -INFINITY;
        for (int j = beg + lane; j < end; j += 32) {
            int s = g_csr_src[j];
            m = fmaxf(m, leaky(g_es1[s] + edv));
        }
#pragma unroll
        for (int o = 16; o; o >>= 1) m = fmaxf(m, __shfl_xor_sync(0xffffffffu, m, o));
        // pass 2: weighted aggregate, lanes across 128 features
        float a0 = 0.f, a1 = 0.f, a2 = 0.f, a3 = 0.f, d = 0.f;
        for (int j = beg; j < end; j++) {
            int s = g_csr_src[j];
            float e = leaky(g_es1[s] + edv);
            float w = expf(e - m);
            d += w;
            const float* hp = g_h + (size_t)s * F_HID;
            a0 += w * hp[lane];
            a1 += w * hp[lane + 32];
            a2 += w * hp[lane + 64];
            a3 += w * hp[lane + 96];
        }
        float inv = 1.f / fmaxf(d, 1e-16f);
        a0 = fmaxf(a0 * inv, 0.f);  // relu(h1)
        a1 = fmaxf(a1 * inv, 0.f);
        a2 = fmaxf(a2 * inv, 0.f);
        a3 = fmaxf(a3 * inv, 0.f);
        // h2 = h1 @ W_mu (128x2)
        int f0 = lane, f1 = lane + 32, f2 = lane + 64, f3 = lane + 96;
        h2_0 = a0 * Wmu[f0 * 2]     + a1 * Wmu[f1 * 2]     + a2 * Wmu[f2 * 2]     + a3 * Wmu[f3 * 2];
        h2_1 = a0 * Wmu[f0 * 2 + 1] + a1 * Wmu[f1 * 2 + 1] + a2 * Wmu[f2 * 2 + 1] + a3 * Wmu[f3 * 2 + 1];
#pragma unroll
        for (int o = 16; o; o >>= 1) {
            h2_0 += __shfl_xor_sync(0xffffffffu, h2_0, o);
            h2_1 += __shfl_xor_sync(0xffffffffu, h2_1, o);
        }
    }
    if (lane == 0) {
        g_h2[2 * v] = h2_0;
        g_h2[2 * v + 1] = h2_1;
        g_es2[v] = h2_0 * amus[0] + h2_1 * amus[1];
        g_ed2[v] = h2_0 * amud[0] + h2_1 * amud[1];
    }
}

// ---------------- layer-2 aggregation -> mu (written straight to output tail) ----------------
__global__ __launch_bounds__(256) void agg2_k(float* __restrict__ mu_out) {
    int warp = (blockIdx.x * blockDim.x + threadIdx.x) >> 5;
    int lane = threadIdx.x & 31;
    if (warp >= N_NODES) return;
    int v = warp;
    int beg = g_off[v], end = g_off[v + 1];
    float mu0 = 0.f, mu1 = 0.f;
    if (beg < end) {
        float edv = g_ed2[v];
        float m = -INFINITY;
        for (int j = beg + lane; j < end; j += 32) {
            int s = g_csr_src[j];
            m = fmaxf(m, leaky(g_es2[s] + edv));
        }
#pragma unroll
        for (int o = 16; o; o >>= 1) m = fmaxf(m, __shfl_xor_sync(0xffffffffu, m, o));
        float d = 0.f, a0 = 0.f, a1 = 0.f;
        for (int j = beg + lane; j < end; j += 32) {
            int s = g_csr_src[j];
            float e = leaky(g_es2[s] + edv);
            float w = expf(e - m);
            d += w;
            a0 += w * g_h2[2 * s];
            a1 += w * g_h2[2 * s + 1];
        }
#pragma unroll
        for (int o = 16; o; o >>= 1) {
            d  += __shfl_xor_sync(0xffffffffu, d, o);
            a0 += __shfl_xor_sync(0xffffffffu, a0, o);
            a1 += __shfl_xor_sync(0xffffffffu, a1, o);
        }
        float inv = 1.f / fmaxf(d, 1e-16f);
        mu0 = a0 * inv;
        mu1 = a1 * inv;
    }
    if (lane == 0) {
        mu_out[2 * v] = mu0;
        mu_out[2 * v + 1] = mu1;
    }
}

// ---------------- sampled-softmax logits ----------------
__global__ __launch_bounds__(256) void logits_k(const float* __restrict__ mu,
                                                const int* __restrict__ input_y,
                                                const int* __restrict__ sample_ids,
                                                const float* __restrict__ ssw,
                                                const float* __restrict__ ssb,
                                                float* __restrict__ out) {
    __shared__ float sw0[N_SAMP], sw1[N_SAMP], sb[N_SAMP];
    for (int i = threadIdx.x; i < N_SAMP; i += blockDim.x) {
        int sid = sample_ids[i];
        sw0[i] = ssw[2 * sid];
        sw1[i] = ssw[2 * sid + 1];
        sb[i] = ssb[sid];
    }
    __syncthreads();
    int warp = (blockIdx.x * blockDim.x + threadIdx.x) >> 5;
    int lane = threadIdx.x & 31;
    if (warp >= N_NODES) return;
    float m0 = mu[2 * warp], m1 = mu[2 * warp + 1];
    float* row = out + (size_t)warp * (N_SAMP + 1);
    if (lane == 0) {
        int y = input_y[warp];
        row[0] = m0 * ssw[2 * y] + m1 * ssw[2 * y + 1] + ssb[y];
    }
    for (int c = lane + 1; c <= N_SAMP; c += 32) {
        int s = c - 1;
        row[c] = m0 * sw0[s] + m1 * sw1[s] + sb[s];
    }
}

// ---------------- launch ----------------
extern "C" void kernel_launch(void* const* d_in, const int* in_sizes, int n_in,
                              void* d_out, int out_size) {
    const float* X         = (const float*)d_in[0];
    const int*   input_y   = (const int*)d_in[2];
    const int*   edge_idx  = (const int*)d_in[3];
    const int*   sample_ids= (const int*)d_in[4];
    const float* W1        = (const float*)d_in[5];
    const float* a1_src    = (const float*)d_in[6];
    const float* a1_dst    = (const float*)d_in[7];
    const float* W_mu      = (const float*)d_in[8];
    const float* amu_src   = (const float*)d_in[9];
    const float* amu_dst   = (const float*)d_in[10];
    const float* ss_weight = (const float*)d_in[14];
    const float* ss_bias   = (const float*)d_in[15];
    float* out = (float*)d_out;

    float* mu_out = out + (size_t)N_NODES * (N_SAMP + 1);

    // CSR build
    zero_counts_k<<<(N_NODES + 255) / 256, 256>>>();
    hist_k<<<(N_EDGES + 255) / 256, 256>>>(edge_idx);
    scan_k<<<1, 1024>>>();
    fill_k<<<(N_EDGES + 255) / 256, 256>>>(edge_idx);

    // layer 1 GEMM + attention dots
    gemm_k<<<(N_NODES + BM - 1) / BM, 256>>>(X, W1);
    int warp_blocks = (N_NODES * 32 + 255) / 256;
    dots_k<<<warp_blocks, 256>>>(a1_src, a1_dst);

    // layer-1 aggregation fused with h2/e2 epilogue
    agg1_k<<<warp_blocks, 256>>>(W_mu, amu_src, amu_dst);

    // layer-2 aggregation -> mu (into output tail)
    agg2_k<<<warp_blocks, 256>>>(mu_out);

    // sampled softmax logits
    logits_k<<<warp_blocks, 256>>>(mu_out, input_y, sample_ids, ss_weight, ss_bias, out);
}

// round 2
// speedup vs baseline: 1.3101x; 1.3101x over previous
#include <cuda_runtime.h>
#include <cuda_bf16.h>
#include <math.h>
#include <stdint.h>

#define N_NODES 100000
#define N_EDGES 1600000
#define F_IN 256
#define F_HID 128
#define VOCAB 100000
#define N_SAMP 512

// ---------------- scratch (static __device__ — no allocations) ----------------
__device__ float g_h[(size_t)N_NODES * F_HID];     // 51.2 MB, fits L2
__device__ float g_es1[N_NODES];
__device__ float g_ed1[N_NODES];
__device__ int   g_counts[N_NODES];
__device__ int   g_off[N_NODES + 1];
__device__ int   g_cursor[N_NODES];
__device__ int   g_csr_src[N_EDGES];
__device__ float g_h2[2 * N_NODES];
__device__ float g_es2[N_NODES];
__device__ float g_ed2[N_NODES];
// bf16-split, transposed W1:  Bt[n][k], n in [0,128), k in [0,256)
__device__ __nv_bfloat16 g_Bt_hi[F_HID * F_IN];
__device__ __nv_bfloat16 g_Bt_lo[F_HID * F_IN];

// ---------------- CSR build ----------------
__global__ void zero_counts_k() {
    int i = blockIdx.x * blockDim.x + threadIdx.x;
    if (i < N_NODES) g_counts[i] = 0;
}

__global__ void hist_k(const int* __restrict__ edge_index) {
    int e = blockIdx.x * blockDim.x + threadIdx.x;
    if (e < N_EDGES) {
        int dst = edge_index[N_EDGES + e];
        atomicAdd(&g_counts[dst], 1);
    }
}

__global__ void scan_k() {
    __shared__ int s[1024];
    const int T = 1024;
    const int CH = (N_NODES + T - 1) / T;
    int t = threadIdx.x;
    int base = t * CH;
    int sum = 0;
    for (int i = 0; i < CH; i++) {
        int x = base + i;
        if (x < N_NODES) sum += g_counts[x];
    }
    s[t] = sum;
    __syncthreads();
    for (int d = 1; d < T; d <<= 1) {
        int v = 0;
        if (t >= d) v = s[t - d];
        __syncthreads();
        s[t] += v;
        __syncthreads();
    }
    int run = (t > 0) ? s[t - 1] : 0;
    for (int i = 0; i < CH; i++) {
        int x = base + i;
        if (x < N_NODES) {
            g_off[x] = run;
            g_cursor[x] = run;
            run += g_counts[x];
        }
    }
    if (t == T - 1) g_off[N_NODES] = run;
}

__global__ void fill_k(const int* __restrict__ edge_index) {
    int e = blockIdx.x * blockDim.x + threadIdx.x;
    if (e < N_EDGES) {
        int src = edge_index[e];
        int dst = edge_index[N_EDGES + e];
        int pos = atomicAdd(&g_cursor[dst], 1);
        g_csr_src[pos] = src;
    }
}

// ---------------- W1 split+transpose prep:  Bt[n][k] = split(W1[k][n]) ----------------
__global__ void b_split_k(const float* __restrict__ W1) {
    int idx = blockIdx.x * blockDim.x + threadIdx.x;   // 0..32767
    if (idx >= F_HID * F_IN) return;
    int n = idx / F_IN;
    int k = idx % F_IN;
    float w = W1[(size_t)k * F_HID + n];
    __nv_bfloat16 hi = __float2bfloat16(w);
    float r = w - __bfloat162float(hi);
    g_Bt_hi[idx] = hi;
    g_Bt_lo[idx] = __float2bfloat16(r);
}

// ---------------- tensor-core GEMM: h = X @ W1 via bf16 2-term split ----------------
// block tile 128(M) x 128(N), K looped in chunks of 32. 8 warps: 4x2 warp grid,
// warp tile 32(M) x 64(N). mma.m16n8k16 row.col f32.bf16.
#define SMEM_STRIDE 40   // bf16 elements per row (32 data + 8 pad) -> conflict-free frags

__device__ __forceinline__ void mma16816(float* d,
                                         uint32_t a0, uint32_t a1, uint32_t a2, uint32_t a3,
                                         uint32_t b0, uint32_t b1) {
    asm volatile(
        "mma.sync.aligned.m16n8k16.row.col.f32.bf16.bf16.f32 "
        "{%0,%1,%2,%3}, {%4,%5,%6,%7}, {%8,%9}, {%0,%1,%2,%3};\n"
        : "+f"(d[0]), "+f"(d[1]), "+f"(d[2]), "+f"(d[3])
        : "r"(a0), "r"(a1), "r"(a2), "r"(a3), "r"(b0), "r"(b1));
}

__global__ __launch_bounds__(256) void gemm_mma_k(const float* __restrict__ A) {
    __shared__ __nv_bfloat16 As_hi[128][SMEM_STRIDE];
    __shared__ __nv_bfloat16 As_lo[128][SMEM_STRIDE];
    __shared__ __nv_bfloat16 Bs_hi[128][SMEM_STRIDE];
    __shared__ __nv_bfloat16 Bs_lo[128][SMEM_STRIDE];

    const int tid = threadIdx.x;
    const int block_row = blockIdx.x * 128;
    const int w = tid >> 5, l = tid & 31;
    const int warp_m = (w >> 1) * 32;
    const int warp_n = (w & 1) * 64;

    float acc[2][8][4];
#pragma unroll
    for (int i = 0; i < 2; i++)
#pragma unroll
        for (int j = 0; j < 8; j++)
#pragma unroll
            for (int q = 0; q < 4; q++) acc[i][j][q] = 0.f;

    const int ar = tid >> 1;            // 0..127 : row within tile
    const int ac = (tid & 1) * 16;      // 0 or 16 : col half

    for (int k0 = 0; k0 < F_IN; k0 += 32) {
        // ---- load & split A tile: 128 x 32 fp32 -> bf16 hi/lo ----
        {
            int gr = block_row + ar;
#pragma unroll
            for (int j = 0; j < 4; j++) {
                float4 v = make_float4(0.f, 0.f, 0.f, 0.f);
                if (gr < N_NODES)
                    v = *(const float4*)(A + (size_t)gr * F_IN + k0 + ac + j * 4);
                float xs[4] = {v.x, v.y, v.z, v.w};
                __nv_bfloat16 hi[4], lo[4];
#pragma unroll
                for (int c = 0; c < 4; c++) {
                    hi[c] = __float2bfloat16(xs[c]);
                    lo[c] = __float2bfloat16(xs[c] - __bfloat162float(hi[c]));
                }
                __nv_bfloat162* ph = (__nv_bfloat162*)&As_hi[ar][ac + j * 4];
                __nv_bfloat162* pl = (__nv_bfloat162*)&As_lo[ar][ac + j * 4];
                ph[0] = __nv_bfloat162(hi[0], hi[1]);
                ph[1] = __nv_bfloat162(hi[2], hi[3]);
                pl[0] = __nv_bfloat162(lo[0], lo[1]);
                pl[1] = __nv_bfloat162(lo[2], lo[3]);
            }
        }
        // ---- load B tiles (already bf16, transposed [n][k]) ----
        {
            const __nv_bfloat16* bh = g_Bt_hi + (size_t)ar * F_IN + k0 + ac;
            const __nv_bfloat16* bl = g_Bt_lo + (size_t)ar * F_IN + k0 + ac;
            *(uint4*)&Bs_hi[ar][ac] = *(const uint4*)bh;
            *(uint4*)&Bs_hi[ar][ac + 8] = *(const uint4*)(bh + 8);
            *(uint4*)&Bs_lo[ar][ac] = *(const uint4*)bl;
            *(uint4*)&Bs_lo[ar][ac + 8] = *(const uint4*)(bl + 8);
        }
        __syncthreads();

#pragma unroll
        for (int ks = 0; ks < 32; ks += 16) {
            const int fr = l >> 2;              // 0..7
            const int fc = ks + (l & 3) * 2;    // k pair base
            // A fragments (hi & lo), 2 m-frags
            uint32_t ah[2][4], al[2][4];
#pragma unroll
            for (int mf = 0; mf < 2; mf++) {
                int r = warp_m + mf * 16 + fr;
                ah[mf][0] = *(const uint32_t*)&As_hi[r][fc];
                ah[mf][1] = *(const uint32_t*)&As_hi[r + 8][fc];
                ah[mf][2] = *(const uint32_t*)&As_hi[r][fc + 8];
                ah[mf][3] = *(const uint32_t*)&As_hi[r + 8][fc + 8];
                al[mf][0] = *(const uint32_t*)&As_lo[r][fc];
                al[mf][1] = *(const uint32_t*)&As_lo[r + 8][fc];
                al[mf][2] = *(const uint32_t*)&As_lo[r][fc + 8];
                al[mf][3] = *(const uint32_t*)&As_lo[r + 8][fc + 8];
            }
#pragma unroll
            for (int nf = 0; nf < 8; nf++) {
                int n = warp_n + nf * 8 + fr;
                uint32_t bh0 = *(const uint32_t*)&Bs_hi[n][fc];
                uint32_t bh1 = *(const uint32_t*)&Bs_hi[n][fc + 8];
                uint32_t bl0 = *(const uint32_t*)&Bs_lo[n][fc];
                uint32_t bl1 = *(const uint32_t*)&Bs_lo[n][fc + 8];
#pragma unroll
                for (int mf = 0; mf < 2; mf++) {
                    mma16816(acc[mf][nf], ah[mf][0], ah[mf][1], ah[mf][2], ah[mf][3], bh0, bh1);
                    mma16816(acc[mf][nf], ah[mf][0], ah[mf][1], ah[mf][2], ah[mf][3], bl0, bl1);
                    mma16816(acc[mf][nf], al[mf][0], al[mf][1], al[mf][2], al[mf][3], bh0, bh1);
                }
            }
        }
        __syncthreads();
    }

    // ---- epilogue: write h ----
#pragma unroll
    for (int mf = 0; mf < 2; mf++) {
        int r0 = block_row + warp_m + mf * 16 + (l >> 2);
        int r1 = r0 + 8;
#pragma unroll
        for (int nf = 0; nf < 8; nf++) {
            int cc = warp_n + nf * 8 + (l & 3) * 2;
            if (r0 < N_NODES)
                *(float2*)&g_h[(size_t)r0 * F_HID + cc] = make_float2(acc[mf][nf][0], acc[mf][nf][1]);
            if (r1 < N_NODES)
                *(float2*)&g_h[(size_t)r1 * F_HID + cc] = make_float2(acc[mf][nf][2], acc[mf][nf][3]);
        }
    }
}

// ---------------- attention dots: e_src/e_dst per node ----------------
__global__ void dots_k(const float* __restrict__ a_src, const float* __restrict__ a_dst) {
    int warp = (blockIdx.x * blockDim.x + threadIdx.x) >> 5;
    int lane = threadIdx.x & 31;
    if (warp >= N_NODES) return;
    const float* hp = g_h + (size_t)warp * F_HID;
    float es = 0.f, ed = 0.f;
#pragma unroll
    for (int k = 0; k < 4; k++) {
        int f = lane + 32 * k;
        float hv = hp[f];
        es += hv * a_src[f];
        ed += hv * a_dst[f];
    }
#pragma unroll
    for (int o = 16; o; o >>= 1) {
        es += __shfl_xor_sync(0xffffffffu, es, o);
        ed += __shfl_xor_sync(0xffffffffu, ed, o);
    }
    if (lane == 0) {
        g_es1[warp] = es;
        g_ed1[warp] = ed;
    }
}

__device__ __forceinline__ float leaky(float x) { return x > 0.f ? x : 0.2f * x; }

// ---------------- layer-1 aggregation + fused h2/e2 epilogue ----------------
__global__ __launch_bounds__(256) void agg1_k(const float* __restrict__ Wmu,
                                              const float* __restrict__ amus,
                                              const float* __restrict__ amud) {
    int warp = (blockIdx.x * blockDim.x + threadIdx.x) >> 5;
    int lane = threadIdx.x & 31;
    if (warp >= N_NODES) return;
    int v = warp;
    int beg = g_off[v], end = g_off[v + 1];
    float h2_0 = 0.f, h2_1 = 0.f;
    if (beg < end) {
        float edv = g_ed1[v];
        float m = -INFINITY;
        for (int j = beg + lane; j < end; j += 32) {
            int s = g_csr_src[j];
            m = fmaxf(m, leaky(g_es1[s] + edv));
        }
#pragma unroll
        for (int o = 16; o; o >>= 1) m = fmaxf(m, __shfl_xor_sync(0xffffffffu, m, o));
        float a0 = 0.f, a1 = 0.f, a2 = 0.f, a3 = 0.f, d = 0.f;
        for (int j = beg; j < end; j++) {
            int s = g_csr_src[j];
            float e = leaky(g_es1[s] + edv);
            float wgt = expf(e - m);
            d += wgt;
            const float* hp = g_h + (size_t)s * F_HID;
            a0 += wgt * hp[lane];
            a1 += wgt * hp[lane + 32];
            a2 += wgt * hp[lane + 64];
            a3 += wgt * hp[lane + 96];
        }
        float inv = 1.f / fmaxf(d, 1e-16f);
        a0 = fmaxf(a0 * inv, 0.f);
        a1 = fmaxf(a1 * inv, 0.f);
        a2 = fmaxf(a2 * inv, 0.f);
        a3 = fmaxf(a3 * inv, 0.f);
        int f0 = lane, f1 = lane + 32, f2 = lane + 64, f3 = lane + 96;
        h2_0 = a0 * Wmu[f0 * 2]     + a1 * Wmu[f1 * 2]     + a2 * Wmu[f2 * 2]     + a3 * Wmu[f3 * 2];
        h2_1 = a0 * Wmu[f0 * 2 + 1] + a1 * Wmu[f1 * 2 + 1] + a2 * Wmu[f2 * 2 + 1] + a3 * Wmu[f3 * 2 + 1];
#pragma unroll
        for (int o = 16; o; o >>= 1) {
            h2_0 += __shfl_xor_sync(0xffffffffu, h2_0, o);
            h2_1 += __shfl_xor_sync(0xffffffffu, h2_1, o);
        }
    }
    if (lane == 0) {
        g_h2[2 * v] = h2_0;
        g_h2[2 * v + 1] = h2_1;
        g_es2[v] = h2_0 * amus[0] + h2_1 * amus[1];
        g_ed2[v] = h2_0 * amud[0] + h2_1 * amud[1];
    }
}

// ---------------- layer-2 aggregation -> mu ----------------
__global__ __launch_bounds__(256) void agg2_k(float* __restrict__ mu_out) {
    int warp = (blockIdx.x * blockDim.x + threadIdx.x) >> 5;
    int lane = threadIdx.x & 31;
    if (warp >= N_NODES) return;
    int v = warp;
    int beg = g_off[v], end = g_off[v + 1];
    float mu0 = 0.f, mu1 = 0.f;
    if (beg < end) {
        float edv = g_ed2[v];
        float m = -INFINITY;
        for (int j = beg + lane; j < end; j += 32) {
            int s = g_csr_src[j];
            m = fmaxf(m, leaky(g_es2[s] + edv));
        }
#pragma unroll
        for (int o = 16; o; o >>= 1) m = fmaxf(m, __shfl_xor_sync(0xffffffffu, m, o));
        float d = 0.f, a0 = 0.f, a1 = 0.f;
        for (int j = beg + lane; j < end; j += 32) {
            int s = g_csr_src[j];
            float e = leaky(g_es2[s] + edv);
            float wgt = expf(e - m);
            d += wgt;
            a0 += wgt * g_h2[2 * s];
            a1 += wgt * g_h2[2 * s + 1];
        }
#pragma unroll
        for (int o = 16; o; o >>= 1) {
            d  += __shfl_xor_sync(0xffffffffu, d, o);
            a0 += __shfl_xor_sync(0xffffffffu, a0, o);
            a1 += __shfl_xor_sync(0xffffffffu, a1, o);
        }
        float inv = 1.f / fmaxf(d, 1e-16f);
        mu0 = a0 * inv;
        mu1 = a1 * inv;
    }
    if (lane == 0) {
        mu_out[2 * v] = mu0;
        mu_out[2 * v + 1] = mu1;
    }
}

// ---------------- sampled-softmax logits ----------------
__global__ __launch_bounds__(256) void logits_k(const float* __restrict__ mu,
                                                const int* __restrict__ input_y,
                                                const int* __restrict__ sample_ids,
                                                const float* __restrict__ ssw,
                                                const float* __restrict__ ssb,
                                                float* __restrict__ out) {
    __shared__ float sw0[N_SAMP], sw1[N_SAMP], sb[N_SAMP];
    for (int i = threadIdx.x; i < N_SAMP; i += blockDim.x) {
        int sid = sample_ids[i];
        sw0[i] = ssw[2 * sid];
        sw1[i] = ssw[2 * sid + 1];
        sb[i] = ssb[sid];
    }
    __syncthreads();
    int warp = (blockIdx.x * blockDim.x + threadIdx.x) >> 5;
    int lane = threadIdx.x & 31;
    if (warp >= N_NODES) return;
    float m0 = mu[2 * warp], m1 = mu[2 * warp + 1];
    float* row = out + (size_t)warp * (N_SAMP + 1);
    if (lane == 0) {
        int y = input_y[warp];
        row[0] = m0 * ssw[2 * y] + m1 * ssw[2 * y + 1] + ssb[y];
    }
    for (int c = lane + 1; c <= N_SAMP; c += 32) {
        int s = c - 1;
        row[c] = m0 * sw0[s] + m1 * sw1[s] + sb[s];
    }
}

// ---------------- launch ----------------
extern "C" void kernel_launch(void* const* d_in, const int* in_sizes, int n_in,
                              void* d_out, int out_size) {
    const float* X         = (const float*)d_in[0];
    const int*   input_y   = (const int*)d_in[2];
    const int*   edge_idx  = (const int*)d_in[3];
    const int*   sample_ids= (const int*)d_in[4];
    const float* W1        = (const float*)d_in[5];
    const float* a1_src    = (const float*)d_in[6];
    const float* a1_dst    = (const float*)d_in[7];
    const float* W_mu      = (const float*)d_in[8];
    const float* amu_src   = (const float*)d_in[9];
    const float* amu_dst   = (const float*)d_in[10];
    const float* ss_weight = (const float*)d_in[14];
    const float* ss_bias   = (const float*)d_in[15];
    float* out = (float*)d_out;

    float* mu_out = out + (size_t)N_NODES * (N_SAMP + 1);

    // CSR build + W1 split (independent of GEMM)
    zero_counts_k<<<(N_NODES + 255) / 256, 256>>>();
    hist_k<<<(N_EDGES + 255) / 256, 256>>>(edge_idx);
    b_split_k<<<(F_HID * F_IN + 255) / 256, 256>>>(W1);
    scan_k<<<1, 1024>>>();
    fill_k<<<(N_EDGES + 255) / 256, 256>>>(edge_idx);

    // tensor-core GEMM
    gemm_mma_k<<<(N_NODES + 127) / 128, 256>>>(X);

    int warp_blocks = (N_NODES * 32 + 255) / 256;
    dots_k<<<warp_blocks, 256>>>(a1_src, a1_dst);
    agg1_k<<<warp_blocks, 256>>>(W_mu, amu_src, amu_dst);
    agg2_k<<<warp_blocks, 256>>>(mu_out);
    logits_k<<<warp_blocks, 256>>>(mu_out, input_y, sample_ids, ss_weight, ss_bias, out);
}

// round 3
// speedup vs baseline: 1.8635x; 1.4224x over previous
#include <cuda_runtime.h>
#include <cuda_bf16.h>
#include <math.h>
#include <stdint.h>

#define N_NODES 100000
#define N_EDGES 1600000
#define F_IN 256
#define F_HID 128
#define VOCAB 100000
#define N_SAMP 512

#define SCAN_B 256
#define SCAN_NB ((N_NODES + SCAN_B - 1) / SCAN_B)   // 391

// ---------------- scratch (static __device__ — no allocations) ----------------
__device__ float g_h[(size_t)N_NODES * F_HID];     // 51.2 MB, fits L2
__device__ float g_es1[N_NODES];
__device__ float g_ed1[N_NODES];
__device__ int   g_counts[N_NODES];
__device__ int   g_off[N_NODES + 1];
__device__ int   g_cursor[N_NODES];
__device__ int   g_csr_src[N_EDGES];
__device__ float g_h2[2 * N_NODES];
__device__ float g_es2[N_NODES];
__device__ float g_ed2[N_NODES];
__device__ int   g_bsum[SCAN_NB];
__device__ int   g_boff[SCAN_NB];
// bf16-split, transposed W1:  Bt[n][k]
__device__ __nv_bfloat16 g_Bt_hi[F_HID * F_IN];
__device__ __nv_bfloat16 g_Bt_lo[F_HID * F_IN];

// ---------------- CSR build ----------------
__global__ void zero_counts_k() {
    int i = blockIdx.x * blockDim.x + threadIdx.x;
    if (i < N_NODES) g_counts[i] = 0;
}

__global__ void hist_k(const int* __restrict__ edge_index) {
    int e = blockIdx.x * blockDim.x + threadIdx.x;
    if (e < N_EDGES) {
        int dst = edge_index[N_EDGES + e];
        atomicAdd(&g_counts[dst], 1);
    }
}

// phase 1: per-block sums
__global__ __launch_bounds__(SCAN_B) void bsum_k() {
    int i = blockIdx.x * SCAN_B + threadIdx.x;
    int c = (i < N_NODES) ? g_counts[i] : 0;
#pragma unroll
    for (int o = 16; o; o >>= 1) c += __shfl_xor_sync(0xffffffffu, c, o);
    __shared__ int ws[SCAN_B / 32];
    if ((threadIdx.x & 31) == 0) ws[threadIdx.x >> 5] = c;
    __syncthreads();
    if (threadIdx.x < SCAN_B / 32) {
        int v = ws[threadIdx.x];
#pragma unroll
        for (int o = SCAN_B / 64; o; o >>= 1) v += __shfl_xor_sync(0xffffffffu, v, o);
        if (threadIdx.x == 0) g_bsum[blockIdx.x] = v;
    }
}

// phase 2: scan block sums (single small block)
__global__ __launch_bounds__(512) void scan_bsums_k() {
    __shared__ int s[512];
    int t = threadIdx.x;
    int v = (t < SCAN_NB) ? g_bsum[t] : 0;
    s[t] = v;
    __syncthreads();
    for (int d = 1; d < 512; d <<= 1) {
        int x = 0;
        if (t >= d) x = s[t - d];
        __syncthreads();
        s[t] += x;
        __syncthreads();
    }
    if (t < SCAN_NB) g_boff[t] = s[t] - v;   // exclusive
    if (t == 511) g_off[N_NODES] = s[SCAN_NB - 1];
}

// phase 3: intra-block exclusive scan + block offset
__global__ __launch_bounds__(SCAN_B) void write_off_k() {
    int i = blockIdx.x * SCAN_B + threadIdx.x;
    int lane = threadIdx.x & 31;
    int wid = threadIdx.x >> 5;
    int c = (i < N_NODES) ? g_counts[i] : 0;
    // inclusive warp scan
    int inc = c;
#pragma unroll
    for (int d = 1; d < 32; d <<= 1) {
        int x = __shfl_up_sync(0xffffffffu, inc, d);
        if (lane >= d) inc += x;
    }
    __shared__ int wsum[SCAN_B / 32];
    if (lane == 31) wsum[wid] = inc;
    __syncthreads();
    if (threadIdx.x == 0) {
        int run = 0;
#pragma unroll
        for (int wv = 0; wv < SCAN_B / 32; wv++) {
            int x = wsum[wv];
            wsum[wv] = run;
            run += x;
        }
    }
    __syncthreads();
    int off = g_boff[blockIdx.x] + wsum[wid] + inc - c;  // exclusive
    if (i < N_NODES) {
        g_off[i] = off;
        g_cursor[i] = off;
    }
}

__global__ void fill_k(const int* __restrict__ edge_index) {
    int e = blockIdx.x * blockDim.x + threadIdx.x;
    if (e < N_EDGES) {
        int src = edge_index[e];
        int dst = edge_index[N_EDGES + e];
        int pos = atomicAdd(&g_cursor[dst], 1);
        g_csr_src[pos] = src;
    }
}

// ---------------- W1 split+transpose prep ----------------
__global__ void b_split_k(const float* __restrict__ W1) {
    int idx = blockIdx.x * blockDim.x + threadIdx.x;
    if (idx >= F_HID * F_IN) return;
    int n = idx / F_IN;
    int k = idx % F_IN;
    float w = W1[(size_t)k * F_HID + n];
    __nv_bfloat16 hi = __float2bfloat16(w);
    float r = w - __bfloat162float(hi);
    g_Bt_hi[idx] = hi;
    g_Bt_lo[idx] = __float2bfloat16(r);
}

// ---------------- tensor-core GEMM: h = X @ W1 via bf16 2-term split ----------------
#define SMEM_STRIDE 40

__device__ __forceinline__ void mma16816(float* d,
                                         uint32_t a0, uint32_t a1, uint32_t a2, uint32_t a3,
                                         uint32_t b0, uint32_t b1) {
    asm volatile(
        "mma.sync.aligned.m16n8k16.row.col.f32.bf16.bf16.f32 "
        "{%0,%1,%2,%3}, {%4,%5,%6,%7}, {%8,%9}, {%0,%1,%2,%3};\n"
        : "+f"(d[0]), "+f"(d[1]), "+f"(d[2]), "+f"(d[3])
        : "r"(a0), "r"(a1), "r"(a2), "r"(a3), "r"(b0), "r"(b1));
}

__global__ __launch_bounds__(256) void gemm_mma_k(const float* __restrict__ A) {
    __shared__ __nv_bfloat16 As_hi[128][SMEM_STRIDE];
    __shared__ __nv_bfloat16 As_lo[128][SMEM_STRIDE];
    __shared__ __nv_bfloat16 Bs_hi[128][SMEM_STRIDE];
    __shared__ __nv_bfloat16 Bs_lo[128][SMEM_STRIDE];

    const int tid = threadIdx.x;
    const int block_row = blockIdx.x * 128;
    const int w = tid >> 5, l = tid & 31;
    const int warp_m = (w >> 1) * 32;
    const int warp_n = (w & 1) * 64;

    float acc[2][8][4];
#pragma unroll
    for (int i = 0; i < 2; i++)
#pragma unroll
        for (int j = 0; j < 8; j++)
#pragma unroll
            for (int q = 0; q < 4; q++) acc[i][j][q] = 0.f;

    const int ar = tid >> 1;
    const int ac = (tid & 1) * 16;

    for (int k0 = 0; k0 < F_IN; k0 += 32) {
        {
            int gr = block_row + ar;
#pragma unroll
            for (int j = 0; j < 4; j++) {
                float4 v = make_float4(0.f, 0.f, 0.f, 0.f);
                if (gr < N_NODES)
                    v = *(const float4*)(A + (size_t)gr * F_IN + k0 + ac + j * 4);
                float xs[4] = {v.x, v.y, v.z, v.w};
                __nv_bfloat16 hi[4], lo[4];
#pragma unroll
                for (int c = 0; c < 4; c++) {
                    hi[c] = __float2bfloat16(xs[c]);
                    lo[c] = __float2bfloat16(xs[c] - __bfloat162float(hi[c]));
                }
                __nv_bfloat162* ph = (__nv_bfloat162*)&As_hi[ar][ac + j * 4];
                __nv_bfloat162* pl = (__nv_bfloat162*)&As_lo[ar][ac + j * 4];
                ph[0] = __nv_bfloat162(hi[0], hi[1]);
                ph[1] = __nv_bfloat162(hi[2], hi[3]);
                pl[0] = __nv_bfloat162(lo[0], lo[1]);
                pl[1] = __nv_bfloat162(lo[2], lo[3]);
            }
        }
        {
            const __nv_bfloat16* bh = g_Bt_hi + (size_t)ar * F_IN + k0 + ac;
            const __nv_bfloat16* bl = g_Bt_lo + (size_t)ar * F_IN + k0 + ac;
            *(uint4*)&Bs_hi[ar][ac] = *(const uint4*)bh;
            *(uint4*)&Bs_hi[ar][ac + 8] = *(const uint4*)(bh + 8);
            *(uint4*)&Bs_lo[ar][ac] = *(const uint4*)bl;
            *(uint4*)&Bs_lo[ar][ac + 8] = *(const uint4*)(bl + 8);
        }
        __syncthreads();

#pragma unroll
        for (int ks = 0; ks < 32; ks += 16) {
            const int fr = l >> 2;
            const int fc = ks + (l & 3) * 2;
            uint32_t ah[2][4], al[2][4];
#pragma unroll
            for (int mf = 0; mf < 2; mf++) {
                int r = warp_m + mf * 16 + fr;
                ah[mf][0] = *(const uint32_t*)&As_hi[r][fc];
                ah[mf][1] = *(const uint32_t*)&As_hi[r + 8][fc];
                ah[mf][2] = *(const uint32_t*)&As_hi[r][fc + 8];
                ah[mf][3] = *(const uint32_t*)&As_hi[r + 8][fc + 8];
                al[mf][0] = *(const uint32_t*)&As_lo[r][fc];
                al[mf][1] = *(const uint32_t*)&As_lo[r + 8][fc];
                al[mf][2] = *(const uint32_t*)&As_lo[r][fc + 8];
                al[mf][3] = *(const uint32_t*)&As_lo[r + 8][fc + 8];
            }
#pragma unroll
            for (int nf = 0; nf < 8; nf++) {
                int n = warp_n + nf * 8 + fr;
                uint32_t bh0 = *(const uint32_t*)&Bs_hi[n][fc];
                uint32_t bh1 = *(const uint32_t*)&Bs_hi[n][fc + 8];
                uint32_t bl0 = *(const uint32_t*)&Bs_lo[n][fc];
                uint32_t bl1 = *(const uint32_t*)&Bs_lo[n][fc + 8];
#pragma unroll
                for (int mf = 0; mf < 2; mf++) {
                    mma16816(acc[mf][nf], ah[mf][0], ah[mf][1], ah[mf][2], ah[mf][3], bh0, bh1);
                    mma16816(acc[mf][nf], ah[mf][0], ah[mf][1], ah[mf][2], ah[mf][3], bl0, bl1);
                    mma16816(acc[mf][nf], al[mf][0], al[mf][1], al[mf][2], al[mf][3], bh0, bh1);
                }
            }
        }
        __syncthreads();
    }

#pragma unroll
    for (int mf = 0; mf < 2; mf++) {
        int r0 = block_row + warp_m + mf * 16 + (l >> 2);
        int r1 = r0 + 8;
#pragma unroll
        for (int nf = 0; nf < 8; nf++) {
            int cc = warp_n + nf * 8 + (l & 3) * 2;
            if (r0 < N_NODES)
                *(float2*)&g_h[(size_t)r0 * F_HID + cc] = make_float2(acc[mf][nf][0], acc[mf][nf][1]);
            if (r1 < N_NODES)
                *(float2*)&g_h[(size_t)r1 * F_HID + cc] = make_float2(acc[mf][nf][2], acc[mf][nf][3]);
        }
    }
}

// ---------------- attention dots ----------------
__global__ void dots_k(const float* __restrict__ a_src, const float* __restrict__ a_dst) {
    int warp = (blockIdx.x * blockDim.x + threadIdx.x) >> 5;
    int lane = threadIdx.x & 31;
    if (warp >= N_NODES) return;
    const float* hp = g_h + (size_t)warp * F_HID;
    float es = 0.f, ed = 0.f;
#pragma unroll
    for (int k = 0; k < 4; k++) {
        int f = lane + 32 * k;
        float hv = hp[f];
        es += hv * a_src[f];
        ed += hv * a_dst[f];
    }
#pragma unroll
    for (int o = 16; o; o >>= 1) {
        es += __shfl_xor_sync(0xffffffffu, es, o);
        ed += __shfl_xor_sync(0xffffffffu, ed, o);
    }
    if (lane == 0) {
        g_es1[warp] = es;
        g_ed1[warp] = ed;
    }
}

__device__ __forceinline__ float leaky(float x) { return x > 0.f ? x : 0.2f * x; }

// ---------------- layer-1 aggregation + fused h2/e2 epilogue ----------------
__global__ __launch_bounds__(256) void agg1_k(const float* __restrict__ Wmu,
                                              const float* __restrict__ amus,
                                              const float* __restrict__ amud) {
    int warp = (blockIdx.x * blockDim.x + threadIdx.x) >> 5;
    int lane = threadIdx.x & 31;
    if (warp >= N_NODES) return;
    int v = warp;
    int beg = g_off[v], end = g_off[v + 1];
    float h2_0 = 0.f, h2_1 = 0.f;
    if (beg < end) {
        float edv = g_ed1[v];
        float m = -INFINITY;
        for (int j = beg + lane; j < end; j += 32) {
            int s = g_csr_src[j];
            m = fmaxf(m, leaky(g_es1[s] + edv));
        }
#pragma unroll
        for (int o = 16; o; o >>= 1) m = fmaxf(m, __shfl_xor_sync(0xffffffffu, m, o));
        float a0 = 0.f, a1 = 0.f, a2 = 0.f, a3 = 0.f, d = 0.f;
        for (int j = beg; j < end; j++) {
            int s = g_csr_src[j];
            float e = leaky(g_es1[s] + edv);
            float wgt = expf(e - m);
            d += wgt;
            const float* hp = g_h + (size_t)s * F_HID;
            a0 += wgt * hp[lane];
            a1 += wgt * hp[lane + 32];
            a2 += wgt * hp[lane + 64];
            a3 += wgt * hp[lane + 96];
        }
        float inv = 1.f / fmaxf(d, 1e-16f);
        a0 = fmaxf(a0 * inv, 0.f);
        a1 = fmaxf(a1 * inv, 0.f);
        a2 = fmaxf(a2 * inv, 0.f);
        a3 = fmaxf(a3 * inv, 0.f);
        int f0 = lane, f1 = lane + 32, f2 = lane + 64, f3 = lane + 96;
        h2_0 = a0 * Wmu[f0 * 2]     + a1 * Wmu[f1 * 2]     + a2 * Wmu[f2 * 2]     + a3 * Wmu[f3 * 2];
        h2_1 = a0 * Wmu[f0 * 2 + 1] + a1 * Wmu[f1 * 2 + 1] + a2 * Wmu[f2 * 2 + 1] + a3 * Wmu[f3 * 2 + 1];
#pragma unroll
        for (int o = 16; o; o >>= 1) {
            h2_0 += __shfl_xor_sync(0xffffffffu, h2_0, o);
            h2_1 += __shfl_xor_sync(0xffffffffu, h2_1, o);
        }
    }
    if (lane == 0) {
        g_h2[2 * v] = h2_0;
        g_h2[2 * v + 1] = h2_1;
        g_es2[v] = h2_0 * amus[0] + h2_1 * amus[1];
        g_ed2[v] = h2_0 * amud[0] + h2_1 * amud[1];
    }
}

// ---------------- layer-2 aggregation -> mu ----------------
__global__ __launch_bounds__(256) void agg2_k(float* __restrict__ mu_out) {
    int warp = (blockIdx.x * blockDim.x + threadIdx.x) >> 5;
    int lane = threadIdx.x & 31;
    if (warp >= N_NODES) return;
    int v = warp;
    int beg = g_off[v], end = g_off[v + 1];
    float mu0 = 0.f, mu1 = 0.f;
    if (beg < end) {
        float edv = g_ed2[v];
        float m = -INFINITY;
        for (int j = beg + lane; j < end; j += 32) {
            int s = g_csr_src[j];
            m = fmaxf(m, leaky(g_es2[s] + edv));
        }
#pragma unroll
        for (int o = 16; o; o >>= 1) m = fmaxf(m, __shfl_xor_sync(0xffffffffu, m, o));
        float d = 0.f, a0 = 0.f, a1 = 0.f;
        for (int j = beg + lane; j < end; j += 32) {
            int s = g_csr_src[j];
            float e = leaky(g_es2[s] + edv);
            float wgt = expf(e - m);
            d += wgt;
            a0 += wgt * g_h2[2 * s];
            a1 += wgt * g_h2[2 * s + 1];
        }
#pragma unroll
        for (int o = 16; o; o >>= 1) {
            d  += __shfl_xor_sync(0xffffffffu, d, o);
            a0 += __shfl_xor_sync(0xffffffffu, a0, o);
            a1 += __shfl_xor_sync(0xffffffffu, a1, o);
        }
        float inv = 1.f / fmaxf(d, 1e-16f);
        mu0 = a0 * inv;
        mu1 = a1 * inv;
    }
    if (lane == 0) {
        mu_out[2 * v] = mu0;
        mu_out[2 * v + 1] = mu1;
    }
}

// ---------------- sampled-softmax logits ----------------
__global__ __launch_bounds__(256) void logits_k(const float* __restrict__ mu,
                                                const int* __restrict__ input_y,
                                                const int* __restrict__ sample_ids,
                                                const float* __restrict__ ssw,
                                                const float* __restrict__ ssb,
                                                float* __restrict__ out) {
    __shared__ float sw0[N_SAMP], sw1[N_SAMP], sb[N_SAMP];
    for (int i = threadIdx.x; i < N_SAMP; i += blockDim.x) {
        int sid = sample_ids[i];
        sw0[i] = ssw[2 * sid];
        sw1[i] = ssw[2 * sid + 1];
        sb[i] = ssb[sid];
    }
    __syncthreads();
    int warp = (blockIdx.x * blockDim.x + threadIdx.x) >> 5;
    int lane = threadIdx.x & 31;
    if (warp >= N_NODES) return;
    float m0 = mu[2 * warp], m1 = mu[2 * warp + 1];
    float* row = out + (size_t)warp * (N_SAMP + 1);
    if (lane == 0) {
        int y = input_y[warp];
        row[0] = m0 * ssw[2 * y] + m1 * ssw[2 * y + 1] + ssb[y];
    }
    for (int c = lane + 1; c <= N_SAMP; c += 32) {
        int s = c - 1;
        row[c] = m0 * sw0[s] + m1 * sw1[s] + sb[s];
    }
}

// ---------------- launch ----------------
extern "C" void kernel_launch(void* const* d_in, const int* in_sizes, int n_in,
                              void* d_out, int out_size) {
    const float* X         = (const float*)d_in[0];
    const int*   input_y   = (const int*)d_in[2];
    const int*   edge_idx  = (const int*)d_in[3];
    const int*   sample_ids= (const int*)d_in[4];
    const float* W1        = (const float*)d_in[5];
    const float* a1_src    = (const float*)d_in[6];
    const float* a1_dst    = (const float*)d_in[7];
    const float* W_mu      = (const float*)d_in[8];
    const float* amu_src   = (const float*)d_in[9];
    const float* amu_dst   = (const float*)d_in[10];
    const float* ss_weight = (const float*)d_in[14];
    const float* ss_bias   = (const float*)d_in[15];
    float* out = (float*)d_out;

    float* mu_out = out + (size_t)N_NODES * (N_SAMP + 1);

    // CSR build + W1 split
    zero_counts_k<<<(N_NODES + 255) / 256, 256>>>();
    hist_k<<<(N_EDGES + 255) / 256, 256>>>(edge_idx);
    b_split_k<<<(F_HID * F_IN + 255) / 256, 256>>>(W1);
    bsum_k<<<SCAN_NB, SCAN_B>>>();
    scan_bsums_k<<<1, 512>>>();
    write_off_k<<<SCAN_NB, SCAN_B>>>();
    fill_k<<<(N_EDGES + 255) / 256, 256>>>(edge_idx);

    // tensor-core GEMM
    gemm_mma_k<<<(N_NODES + 127) / 128, 256>>>(X);

    int warp_blocks = (N_NODES * 32 + 255) / 256;
    dots_k<<<warp_blocks, 256>>>(a1_src, a1_dst);
    agg1_k<<<warp_blocks, 256>>>(W_mu, amu_src, amu_dst);
    agg2_k<<<warp_blocks, 256>>>(mu_out);
    logits_k<<<warp_blocks, 256>>>(mu_out, input_y, sample_ids, ss_weight, ss_bias, out);
}

// round 4
// speedup vs baseline: 1.9439x; 1.0431x over previous
#include <cuda_runtime.h>
#include <cuda_bf16.h>
#include <math.h>
#include <stdint.h>

#define N_NODES 100000
#define N_EDGES 1600000
#define F_IN 256
#define F_HID 128
#define VOCAB 100000
#define N_SAMP 512

#define SCAN_B 256
#define SCAN_NB ((N_NODES + SCAN_B - 1) / SCAN_B)   // 391

// ---------------- scratch (static __device__ — no allocations) ----------------
__device__ float g_h[(size_t)N_NODES * F_HID];     // 51.2 MB, fits L2
__device__ float g_es1[N_NODES];
__device__ float g_ed1[N_NODES];
__device__ int   g_counts[N_NODES];
__device__ int   g_off[N_NODES + 1];
__device__ int   g_cursor[N_NODES];
__device__ int   g_csr_src[N_EDGES];
__device__ float g_h2[2 * N_NODES];
__device__ float g_es2[N_NODES];
__device__ float g_ed2[N_NODES];
__device__ int   g_bsum[SCAN_NB];
__device__ int   g_boff[SCAN_NB];
__device__ __nv_bfloat16 g_Bt_hi[F_HID * F_IN];
__device__ __nv_bfloat16 g_Bt_lo[F_HID * F_IN];

// ---------------- CSR build ----------------
__global__ void zero_counts_k() {
    int i = blockIdx.x * blockDim.x + threadIdx.x;
    if (i < N_NODES) g_counts[i] = 0;
}

__global__ void hist_k(const int* __restrict__ edge_index) {
    int e = blockIdx.x * blockDim.x + threadIdx.x;
    if (e < N_EDGES) {
        int dst = edge_index[N_EDGES + e];
        atomicAdd(&g_counts[dst], 1);
    }
}

__global__ __launch_bounds__(SCAN_B) void bsum_k() {
    int i = blockIdx.x * SCAN_B + threadIdx.x;
    int c = (i < N_NODES) ? g_counts[i] : 0;
#pragma unroll
    for (int o = 16; o; o >>= 1) c += __shfl_xor_sync(0xffffffffu, c, o);
    __shared__ int ws[SCAN_B / 32];
    if ((threadIdx.x & 31) == 0) ws[threadIdx.x >> 5] = c;
    __syncthreads();
    if (threadIdx.x < SCAN_B / 32) {
        int v = ws[threadIdx.x];
#pragma unroll
        for (int o = SCAN_B / 64; o; o >>= 1) v += __shfl_xor_sync(0xffffffffu, v, o);
        if (threadIdx.x == 0) g_bsum[blockIdx.x] = v;
    }
}

__global__ __launch_bounds__(512) void scan_bsums_k() {
    __shared__ int s[512];
    int t = threadIdx.x;
    int v = (t < SCAN_NB) ? g_bsum[t] : 0;
    s[t] = v;
    __syncthreads();
    for (int d = 1; d < 512; d <<= 1) {
        int x = 0;
        if (t >= d) x = s[t - d];
        __syncthreads();
        s[t] += x;
        __syncthreads();
    }
    if (t < SCAN_NB) g_boff[t] = s[t] - v;
    if (t == 511) g_off[N_NODES] = s[SCAN_NB - 1];
}

__global__ __launch_bounds__(SCAN_B) void write_off_k() {
    int i = blockIdx.x * SCAN_B + threadIdx.x;
    int lane = threadIdx.x & 31;
    int wid = threadIdx.x >> 5;
    int c = (i < N_NODES) ? g_counts[i] : 0;
    int inc = c;
#pragma unroll
    for (int d = 1; d < 32; d <<= 1) {
        int x = __shfl_up_sync(0xffffffffu, inc, d);
        if (lane >= d) inc += x;
    }
    __shared__ int wsum[SCAN_B / 32];
    if (lane == 31) wsum[wid] = inc;
    __syncthreads();
    if (threadIdx.x == 0) {
        int run = 0;
#pragma unroll
        for (int wv = 0; wv < SCAN_B / 32; wv++) {
            int x = wsum[wv];
            wsum[wv] = run;
            run += x;
        }
    }
    __syncthreads();
    int off = g_boff[blockIdx.x] + wsum[wid] + inc - c;
    if (i < N_NODES) {
        g_off[i] = off;
        g_cursor[i] = off;
    }
}

__global__ void fill_k(const int* __restrict__ edge_index) {
    int e = blockIdx.x * blockDim.x + threadIdx.x;
    if (e < N_EDGES) {
        int src = edge_index[e];
        int dst = edge_index[N_EDGES + e];
        int pos = atomicAdd(&g_cursor[dst], 1);
        g_csr_src[pos] = src;
    }
}

// ---------------- W1 split+transpose prep ----------------
__global__ void b_split_k(const float* __restrict__ W1) {
    int idx = blockIdx.x * blockDim.x + threadIdx.x;
    if (idx >= F_HID * F_IN) return;
    int n = idx / F_IN;
    int k = idx % F_IN;
    float w = W1[(size_t)k * F_HID + n];
    __nv_bfloat16 hi = __float2bfloat16(w);
    float r = w - __bfloat162float(hi);
    g_Bt_hi[idx] = hi;
    g_Bt_lo[idx] = __float2bfloat16(r);
}

// ---------------- tensor-core GEMM + fused attention-dot epilogue ----------------
#define SMEM_STRIDE 40

__device__ __forceinline__ void mma16816(float* d,
                                         uint32_t a0, uint32_t a1, uint32_t a2, uint32_t a3,
                                         uint32_t b0, uint32_t b1) {
    asm volatile(
        "mma.sync.aligned.m16n8k16.row.col.f32.bf16.bf16.f32 "
        "{%0,%1,%2,%3}, {%4,%5,%6,%7}, {%8,%9}, {%0,%1,%2,%3};\n"
        : "+f"(d[0]), "+f"(d[1]), "+f"(d[2]), "+f"(d[3])
        : "r"(a0), "r"(a1), "r"(a2), "r"(a3), "r"(b0), "r"(b1));
}

__global__ __launch_bounds__(256) void gemm_mma_k(const float* __restrict__ A,
                                                  const float* __restrict__ a1_src,
                                                  const float* __restrict__ a1_dst) {
    __shared__ __nv_bfloat16 As_hi[128][SMEM_STRIDE];
    __shared__ __nv_bfloat16 As_lo[128][SMEM_STRIDE];
    __shared__ __nv_bfloat16 Bs_hi[128][SMEM_STRIDE];
    __shared__ __nv_bfloat16 Bs_lo[128][SMEM_STRIDE];
    __shared__ float es_s[128][2], ed_s[128][2];

    const int tid = threadIdx.x;
    const int block_row = blockIdx.x * 128;
    const int w = tid >> 5, l = tid & 31;
    const int warp_m = (w >> 1) * 32;
    const int warp_n = (w & 1) * 64;
    const int nhalf = w & 1;

    float acc[2][8][4];
#pragma unroll
    for (int i = 0; i < 2; i++)
#pragma unroll
        for (int j = 0; j < 8; j++)
#pragma unroll
            for (int q = 0; q < 4; q++) acc[i][j][q] = 0.f;

    const int ar = tid >> 1;
    const int ac = (tid & 1) * 16;

    for (int k0 = 0; k0 < F_IN; k0 += 32) {
        {
            int gr = block_row + ar;
#pragma unroll
            for (int j = 0; j < 4; j++) {
                float4 v = make_float4(0.f, 0.f, 0.f, 0.f);
                if (gr < N_NODES)
                    v = *(const float4*)(A + (size_t)gr * F_IN + k0 + ac + j * 4);
                float xs[4] = {v.x, v.y, v.z, v.w};
                __nv_bfloat16 hi[4], lo[4];
#pragma unroll
                for (int c = 0; c < 4; c++) {
                    hi[c] = __float2bfloat16(xs[c]);
                    lo[c] = __float2bfloat16(xs[c] - __bfloat162float(hi[c]));
                }
                __nv_bfloat162* ph = (__nv_bfloat162*)&As_hi[ar][ac + j * 4];
                __nv_bfloat162* pl = (__nv_bfloat162*)&As_lo[ar][ac + j * 4];
                ph[0] = __nv_bfloat162(hi[0], hi[1]);
                ph[1] = __nv_bfloat162(hi[2], hi[3]);
                pl[0] = __nv_bfloat162(lo[0], lo[1]);
                pl[1] = __nv_bfloat162(lo[2], lo[3]);
            }
        }
        {
            const __nv_bfloat16* bh = g_Bt_hi + (size_t)ar * F_IN + k0 + ac;
            const __nv_bfloat16* bl = g_Bt_lo + (size_t)ar * F_IN + k0 + ac;
            *(uint4*)&Bs_hi[ar][ac] = *(const uint4*)bh;
            *(uint4*)&Bs_hi[ar][ac + 8] = *(const uint4*)(bh + 8);
            *(uint4*)&Bs_lo[ar][ac] = *(const uint4*)bl;
            *(uint4*)&Bs_lo[ar][ac + 8] = *(const uint4*)(bl + 8);
        }
        __syncthreads();

#pragma unroll
        for (int ks = 0; ks < 32; ks += 16) {
            const int fr = l >> 2;
            const int fc = ks + (l & 3) * 2;
            uint32_t ah[2][4], al[2][4];
#pragma unroll
            for (int mf = 0; mf < 2; mf++) {
                int r = warp_m + mf * 16 + fr;
                ah[mf][0] = *(const uint32_t*)&As_hi[r][fc];
                ah[mf][1] = *(const uint32_t*)&As_hi[r + 8][fc];
                ah[mf][2] = *(const uint32_t*)&As_hi[r][fc + 8];
                ah[mf][3] = *(const uint32_t*)&As_hi[r + 8][fc + 8];
                al[mf][0] = *(const uint32_t*)&As_lo[r][fc];
                al[mf][1] = *(const uint32_t*)&As_lo[r + 8][fc];
                al[mf][2] = *(const uint32_t*)&As_lo[r][fc + 8];
                al[mf][3] = *(const uint32_t*)&As_lo[r + 8][fc + 8];
            }
#pragma unroll
            for (int nf = 0; nf < 8; nf++) {
                int n = warp_n + nf * 8 + fr;
                uint32_t bh0 = *(const uint32_t*)&Bs_hi[n][fc];
                uint32_t bh1 = *(const uint32_t*)&Bs_hi[n][fc + 8];
                uint32_t bl0 = *(const uint32_t*)&Bs_lo[n][fc];
                uint32_t bl1 = *(const uint32_t*)&Bs_lo[n][fc + 8];
#pragma unroll
                for (int mf = 0; mf < 2; mf++) {
                    mma16816(acc[mf][nf], ah[mf][0], ah[mf][1], ah[mf][2], ah[mf][3], bh0, bh1);
                    mma16816(acc[mf][nf], ah[mf][0], ah[mf][1], ah[mf][2], ah[mf][3], bl0, bl1);
                    mma16816(acc[mf][nf], al[mf][0], al[mf][1], al[mf][2], al[mf][3], bh0, bh1);
                }
            }
        }
        __syncthreads();
    }

    const int fr = l >> 2;
    const int quad = l & 3;

    // ---- write h + per-warp partial attention dots ----
#pragma unroll
    for (int mf = 0; mf < 2; mf++) {
        int rl0 = warp_m + mf * 16 + fr;
        int rl1 = rl0 + 8;
        int r0 = block_row + rl0;
        int r1 = block_row + rl1;
        float es0 = 0.f, ed0 = 0.f, es1 = 0.f, ed1 = 0.f;
#pragma unroll
        for (int nf = 0; nf < 8; nf++) {
            int cc = warp_n + nf * 8 + quad * 2;
            float as0 = a1_src[cc], as1 = a1_src[cc + 1];
            float ad0 = a1_dst[cc], ad1 = a1_dst[cc + 1];
            es0 += acc[mf][nf][0] * as0 + acc[mf][nf][1] * as1;
            ed0 += acc[mf][nf][0] * ad0 + acc[mf][nf][1] * ad1;
            es1 += acc[mf][nf][2] * as0 + acc[mf][nf][3] * as1;
            ed1 += acc[mf][nf][2] * ad0 + acc[mf][nf][3] * ad1;
            if (r0 < N_NODES)
                *(float2*)&g_h[(size_t)r0 * F_HID + cc] = make_float2(acc[mf][nf][0], acc[mf][nf][1]);
            if (r1 < N_NODES)
                *(float2*)&g_h[(size_t)r1 * F_HID + cc] = make_float2(acc[mf][nf][2], acc[mf][nf][3]);
        }
        // reduce over the 4 quad lanes
#pragma unroll
        for (int o = 1; o <= 2; o <<= 1) {
            es0 += __shfl_xor_sync(0xffffffffu, es0, o);
            ed0 += __shfl_xor_sync(0xffffffffu, ed0, o);
            es1 += __shfl_xor_sync(0xffffffffu, es1, o);
            ed1 += __shfl_xor_sync(0xffffffffu, ed1, o);
        }
        if (quad == 0) {
            es_s[rl0][nhalf] = es0;
            ed_s[rl0][nhalf] = ed0;
            es_s[rl1][nhalf] = es1;
            ed_s[rl1][nhalf] = ed1;
        }
    }
    __syncthreads();
    if (tid < 128) {
        int gr = block_row + tid;
        if (gr < N_NODES) {
            g_es1[gr] = es_s[tid][0] + es_s[tid][1];
            g_ed1[gr] = ed_s[tid][0] + ed_s[tid][1];
        }
    }
}

__device__ __forceinline__ float leaky(float x) { return x > 0.f ? x : 0.2f * x; }

// ---------------- layer-1 aggregation + fused h2/e2 epilogue ----------------
__global__ __launch_bounds__(256) void agg1_k(const float* __restrict__ Wmu,
                                              const float* __restrict__ amus,
                                              const float* __restrict__ amud) {
    int warp = (blockIdx.x * blockDim.x + threadIdx.x) >> 5;
    int lane = threadIdx.x & 31;
    if (warp >= N_NODES) return;
    int v = warp;
    int beg = g_off[v], end = g_off[v + 1];
    float h2_0 = 0.f, h2_1 = 0.f;
    if (beg < end) {
        float edv = g_ed1[v];
        float m = -INFINITY;
        for (int j = beg + lane; j < end; j += 32) {
            int s = g_csr_src[j];
            m = fmaxf(m, leaky(g_es1[s] + edv));
        }
#pragma unroll
        for (int o = 16; o; o >>= 1) m = fmaxf(m, __shfl_xor_sync(0xffffffffu, m, o));
        float a0 = 0.f, a1 = 0.f, a2 = 0.f, a3 = 0.f, d = 0.f;
        int j = beg;
        for (; j + 2 <= end; j += 2) {
            int s0 = g_csr_src[j];
            int s1 = g_csr_src[j + 1];
            float w0 = expf(leaky(g_es1[s0] + edv) - m);
            float w1 = expf(leaky(g_es1[s1] + edv) - m);
            const float* hp0 = g_h + (size_t)s0 * F_HID;
            const float* hp1 = g_h + (size_t)s1 * F_HID;
            float x00 = hp0[lane], x01 = hp0[lane + 32], x02 = hp0[lane + 64], x03 = hp0[lane + 96];
            float x10 = hp1[lane], x11 = hp1[lane + 32], x12 = hp1[lane + 64], x13 = hp1[lane + 96];
            d += w0 + w1;
            a0 += w0 * x00 + w1 * x10;
            a1 += w0 * x01 + w1 * x11;
            a2 += w0 * x02 + w1 * x12;
            a3 += w0 * x03 + w1 * x13;
        }
        if (j < end) {
            int s = g_csr_src[j];
            float wgt = expf(leaky(g_es1[s] + edv) - m);
            const float* hp = g_h + (size_t)s * F_HID;
            d += wgt;
            a0 += wgt * hp[lane];
            a1 += wgt * hp[lane + 32];
            a2 += wgt * hp[lane + 64];
            a3 += wgt * hp[lane + 96];
        }
        float inv = 1.f / fmaxf(d, 1e-16f);
        a0 = fmaxf(a0 * inv, 0.f);
        a1 = fmaxf(a1 * inv, 0.f);
        a2 = fmaxf(a2 * inv, 0.f);
        a3 = fmaxf(a3 * inv, 0.f);
        int f0 = lane, f1 = lane + 32, f2 = lane + 64, f3 = lane + 96;
        h2_0 = a0 * Wmu[f0 * 2]     + a1 * Wmu[f1 * 2]     + a2 * Wmu[f2 * 2]     + a3 * Wmu[f3 * 2];
        h2_1 = a0 * Wmu[f0 * 2 + 1] + a1 * Wmu[f1 * 2 + 1] + a2 * Wmu[f2 * 2 + 1] + a3 * Wmu[f3 * 2 + 1];
#pragma unroll
        for (int o = 16; o; o >>= 1) {
            h2_0 += __shfl_xor_sync(0xffffffffu, h2_0, o);
            h2_1 += __shfl_xor_sync(0xffffffffu, h2_1, o);
        }
    }
    if (lane == 0) {
        g_h2[2 * v] = h2_0;
        g_h2[2 * v + 1] = h2_1;
        g_es2[v] = h2_0 * amus[0] + h2_1 * amus[1];
        g_ed2[v] = h2_0 * amud[0] + h2_1 * amud[1];
    }
}

// ---------------- layer-2 aggregation + sampled-softmax logits (fused) ----------------
__global__ __launch_bounds__(256) void agg2_logits_k(const int* __restrict__ input_y,
                                                     const int* __restrict__ sample_ids,
                                                     const float* __restrict__ ssw,
                                                     const float* __restrict__ ssb,
                                                     float* __restrict__ out,
                                                     float* __restrict__ mu_out) {
    __shared__ float sw0[N_SAMP], sw1[N_SAMP], sb[N_SAMP];
    for (int i = threadIdx.x; i < N_SAMP; i += blockDim.x) {
        int sid = sample_ids[i];
        sw0[i] = ssw[2 * sid];
        sw1[i] = ssw[2 * sid + 1];
        sb[i] = ssb[sid];
    }
    __syncthreads();

    int warp = (blockIdx.x * blockDim.x + threadIdx.x) >> 5;
    int lane = threadIdx.x & 31;
    if (warp >= N_NODES) return;
    int v = warp;
    int beg = g_off[v], end = g_off[v + 1];
    float mu0 = 0.f, mu1 = 0.f;
    if (beg < end) {
        float edv = g_ed2[v];
        float m = -INFINITY;
        for (int j = beg + lane; j < end; j += 32) {
            int s = g_csr_src[j];
            m = fmaxf(m, leaky(g_es2[s] + edv));
        }
#pragma unroll
        for (int o = 16; o; o >>= 1) m = fmaxf(m, __shfl_xor_sync(0xffffffffu, m, o));
        float d = 0.f, a0 = 0.f, a1 = 0.f;
        for (int j = beg + lane; j < end; j += 32) {
            int s = g_csr_src[j];
            float wgt = expf(leaky(g_es2[s] + edv) - m);
            d += wgt;
            a0 += wgt * g_h2[2 * s];
            a1 += wgt * g_h2[2 * s + 1];
        }
#pragma unroll
        for (int o = 16; o; o >>= 1) {
            d  += __shfl_xor_sync(0xffffffffu, d, o);
            a0 += __shfl_xor_sync(0xffffffffu, a0, o);
            a1 += __shfl_xor_sync(0xffffffffu, a1, o);
        }
        float inv = 1.f / fmaxf(d, 1e-16f);
        mu0 = a0 * inv;
        mu1 = a1 * inv;
    }
    // all lanes hold mu0/mu1 (butterfly reduce) or zeros
    float* row = out + (size_t)v * (N_SAMP + 1);
    if (lane == 0) {
        mu_out[2 * v] = mu0;
        mu_out[2 * v + 1] = mu1;
        int y = input_y[v];
        row[0] = mu0 * ssw[2 * y] + mu1 * ssw[2 * y + 1] + ssb[y];
    }
    for (int c = lane + 1; c <= N_SAMP; c += 32) {
        int s = c - 1;
        row[c] = mu0 * sw0[s] + mu1 * sw1[s] + sb[s];
    }
}

// ---------------- launch ----------------
extern "C" void kernel_launch(void* const* d_in, const int* in_sizes, int n_in,
                              void* d_out, int out_size) {
    const float* X         = (const float*)d_in[0];
    const int*   input_y   = (const int*)d_in[2];
    const int*   edge_idx  = (const int*)d_in[3];
    const int*   sample_ids= (const int*)d_in[4];
    const float* W1        = (const float*)d_in[5];
    const float* a1_src    = (const float*)d_in[6];
    const float* a1_dst    = (const float*)d_in[7];
    const float* W_mu      = (const float*)d_in[8];
    const float* amu_src   = (const float*)d_in[9];
    const float* amu_dst   = (const float*)d_in[10];
    const float* ss_weight = (const float*)d_in[14];
    const float* ss_bias   = (const float*)d_in[15];
    float* out = (float*)d_out;

    float* mu_out = out + (size_t)N_NODES * (N_SAMP + 1);

    // CSR build + W1 split
    zero_counts_k<<<(N_NODES + 255) / 256, 256>>>();
    hist_k<<<(N_EDGES + 255) / 256, 256>>>(edge_idx);
    b_split_k<<<(F_HID * F_IN + 255) / 256, 256>>>(W1);
    bsum_k<<<SCAN_NB, SCAN_B>>>();
    scan_bsums_k<<<1, 512>>>();
    write_off_k<<<SCAN_NB, SCAN_B>>>();
    fill_k<<<(N_EDGES + 255) / 256, 256>>>(edge_idx);

    // tensor-core GEMM with fused attention-dot epilogue
    gemm_mma_k<<<(N_NODES + 127) / 128, 256>>>(X, a1_src, a1_dst);

    int warp_blocks = (N_NODES * 32 + 255) / 256;
    agg1_k<<<warp_blocks, 256>>>(W_mu, amu_src, amu_dst);
    agg2_logits_k<<<warp_blocks, 256>>>(input_y, sample_ids, ss_weight, ss_bias, out, mu_out);
}

// round 5
// speedup vs baseline: 2.0388x; 1.0488x over previous
#include <cuda_runtime.h>
#include <cuda_bf16.h>
#include <math.h>
#include <stdint.h>

#define N_NODES 100000
#define N_EDGES 1600000
#define F_IN 256
#define F_HID 128
#define VOCAB 100000
#define N_SAMP 512

#define SCAN_B 256
#define SCAN_NB ((N_NODES + SCAN_B - 1) / SCAN_B)   // 391

// ---------------- scratch (static __device__ — no allocations) ----------------
__device__ float g_h[(size_t)N_NODES * F_HID];     // 51.2 MB, fits L2
__device__ float g_es1[N_NODES];
__device__ float g_ed1[N_NODES];
__device__ int   g_counts[N_NODES];
__device__ int   g_off[N_NODES + 1];
__device__ int   g_cursor[N_NODES];
__device__ int   g_csr_src[N_EDGES];
__device__ float g_h2[2 * N_NODES];
__device__ float g_es2[N_NODES];
__device__ float g_ed2[N_NODES];
__device__ int   g_bsum[SCAN_NB];
__device__ int   g_boff[SCAN_NB];
__device__ __nv_bfloat16 g_Bt_hi[F_HID * F_IN];
__device__ __nv_bfloat16 g_Bt_lo[F_HID * F_IN];

// ---------------- CSR build + W1 split (merged) ----------------
__global__ void zero_split_k(const float* __restrict__ W1) {
    int i = blockIdx.x * blockDim.x + threadIdx.x;
    if (i < N_NODES) g_counts[i] = 0;
    if (i < F_HID * F_IN) {
        int n = i / F_IN;
        int k = i % F_IN;
        float w = W1[(size_t)k * F_HID + n];
        __nv_bfloat16 hi = __float2bfloat16(w);
        float r = w - __bfloat162float(hi);
        g_Bt_hi[i] = hi;
        g_Bt_lo[i] = __float2bfloat16(r);
    }
}

__global__ void hist_k(const int* __restrict__ edge_index) {
    int e = blockIdx.x * blockDim.x + threadIdx.x;
    if (e < N_EDGES) {
        int dst = edge_index[N_EDGES + e];
        atomicAdd(&g_counts[dst], 1);
    }
}

__global__ __launch_bounds__(SCAN_B) void bsum_k() {
    int i = blockIdx.x * SCAN_B + threadIdx.x;
    int c = (i < N_NODES) ? g_counts[i] : 0;
#pragma unroll
    for (int o = 16; o; o >>= 1) c += __shfl_xor_sync(0xffffffffu, c, o);
    __shared__ int ws[SCAN_B / 32];
    if ((threadIdx.x & 31) == 0) ws[threadIdx.x >> 5] = c;
    __syncthreads();
    if (threadIdx.x < SCAN_B / 32) {
        int v = ws[threadIdx.x];
#pragma unroll
        for (int o = SCAN_B / 64; o; o >>= 1) v += __shfl_xor_sync(0xffffffffu, v, o);
        if (threadIdx.x == 0) g_bsum[blockIdx.x] = v;
    }
}

__global__ __launch_bounds__(512) void scan_bsums_k() {
    __shared__ int s[512];
    int t = threadIdx.x;
    int v = (t < SCAN_NB) ? g_bsum[t] : 0;
    s[t] = v;
    __syncthreads();
    for (int d = 1; d < 512; d <<= 1) {
        int x = 0;
        if (t >= d) x = s[t - d];
        __syncthreads();
        s[t] += x;
        __syncthreads();
    }
    if (t < SCAN_NB) g_boff[t] = s[t] - v;
    if (t == 511) g_off[N_NODES] = s[SCAN_NB - 1];
}

__global__ __launch_bounds__(SCAN_B) void write_off_k() {
    int i = blockIdx.x * SCAN_B + threadIdx.x;
    int lane = threadIdx.x & 31;
    int wid = threadIdx.x >> 5;
    int c = (i < N_NODES) ? g_counts[i] : 0;
    int inc = c;
#pragma unroll
    for (int d = 1; d < 32; d <<= 1) {
        int x = __shfl_up_sync(0xffffffffu, inc, d);
        if (lane >= d) inc += x;
    }
    __shared__ int wsum[SCAN_B / 32];
    if (lane == 31) wsum[wid] = inc;
    __syncthreads();
    if (threadIdx.x == 0) {
        int run = 0;
#pragma unroll
        for (int wv = 0; wv < SCAN_B / 32; wv++) {
            int x = wsum[wv];
            wsum[wv] = run;
            run += x;
        }
    }
    __syncthreads();
    int off = g_boff[blockIdx.x] + wsum[wid] + inc - c;
    if (i < N_NODES) {
        g_off[i] = off;
        g_cursor[i] = off;
    }
}

__global__ void fill_k(const int* __restrict__ edge_index) {
    int e = blockIdx.x * blockDim.x + threadIdx.x;
    if (e < N_EDGES) {
        int src = edge_index[e];
        int dst = edge_index[N_EDGES + e];
        int pos = atomicAdd(&g_cursor[dst], 1);
        g_csr_src[pos] = src;
    }
}

// ---------------- tensor-core GEMM + fused attention-dot epilogue ----------------
#define SMEM_STRIDE 40

__device__ __forceinline__ void mma16816(float* d,
                                         uint32_t a0, uint32_t a1, uint32_t a2, uint32_t a3,
                                         uint32_t b0, uint32_t b1) {
    asm volatile(
        "mma.sync.aligned.m16n8k16.row.col.f32.bf16.bf16.f32 "
        "{%0,%1,%2,%3}, {%4,%5,%6,%7}, {%8,%9}, {%0,%1,%2,%3};\n"
        : "+f"(d[0]), "+f"(d[1]), "+f"(d[2]), "+f"(d[3])
        : "r"(a0), "r"(a1), "r"(a2), "r"(a3), "r"(b0), "r"(b1));
}

__global__ __launch_bounds__(256) void gemm_mma_k(const float* __restrict__ A,
                                                  const float* __restrict__ a1_src,
                                                  const float* __restrict__ a1_dst) {
    __shared__ __nv_bfloat16 As_hi[128][SMEM_STRIDE];
    __shared__ __nv_bfloat16 As_lo[128][SMEM_STRIDE];
    __shared__ __nv_bfloat16 Bs_hi[128][SMEM_STRIDE];
    __shared__ __nv_bfloat16 Bs_lo[128][SMEM_STRIDE];
    __shared__ float es_s[128][2], ed_s[128][2];

    const int tid = threadIdx.x;
    const int block_row = blockIdx.x * 128;
    const int w = tid >> 5, l = tid & 31;
    const int warp_m = (w >> 1) * 32;
    const int warp_n = (w & 1) * 64;
    const int nhalf = w & 1;

    float acc[2][8][4];
#pragma unroll
    for (int i = 0; i < 2; i++)
#pragma unroll
        for (int j = 0; j < 8; j++)
#pragma unroll
            for (int q = 0; q < 4; q++) acc[i][j][q] = 0.f;

    const int ar = tid >> 1;
    const int ac = (tid & 1) * 16;

    for (int k0 = 0; k0 < F_IN; k0 += 32) {
        {
            int gr = block_row + ar;
#pragma unroll
            for (int j = 0; j < 4; j++) {
                float4 v = make_float4(0.f, 0.f, 0.f, 0.f);
                if (gr < N_NODES)
                    v = *(const float4*)(A + (size_t)gr * F_IN + k0 + ac + j * 4);
                float xs[4] = {v.x, v.y, v.z, v.w};
                __nv_bfloat16 hi[4], lo[4];
#pragma unroll
                for (int c = 0; c < 4; c++) {
                    hi[c] = __float2bfloat16(xs[c]);
                    lo[c] = __float2bfloat16(xs[c] - __bfloat162float(hi[c]));
                }
                __nv_bfloat162* ph = (__nv_bfloat162*)&As_hi[ar][ac + j * 4];
                __nv_bfloat162* pl = (__nv_bfloat162*)&As_lo[ar][ac + j * 4];
                ph[0] = __nv_bfloat162(hi[0], hi[1]);
                ph[1] = __nv_bfloat162(hi[2], hi[3]);
                pl[0] = __nv_bfloat162(lo[0], lo[1]);
                pl[1] = __nv_bfloat162(lo[2], lo[3]);
            }
        }
        {
            const __nv_bfloat16* bh = g_Bt_hi + (size_t)ar * F_IN + k0 + ac;
            const __nv_bfloat16* bl = g_Bt_lo + (size_t)ar * F_IN + k0 + ac;
            *(uint4*)&Bs_hi[ar][ac] = *(const uint4*)bh;
            *(uint4*)&Bs_hi[ar][ac + 8] = *(const uint4*)(bh + 8);
            *(uint4*)&Bs_lo[ar][ac] = *(const uint4*)bl;
            *(uint4*)&Bs_lo[ar][ac + 8] = *(const uint4*)(bl + 8);
        }
        __syncthreads();

#pragma unroll
        for (int ks = 0; ks < 32; ks += 16) {
            const int fr = l >> 2;
            const int fc = ks + (l & 3) * 2;
            uint32_t ah[2][4], al[2][4];
#pragma unroll
            for (int mf = 0; mf < 2; mf++) {
                int r = warp_m + mf * 16 + fr;
                ah[mf][0] = *(const uint32_t*)&As_hi[r][fc];
                ah[mf][1] = *(const uint32_t*)&As_hi[r + 8][fc];
                ah[mf][2] = *(const uint32_t*)&As_hi[r][fc + 8];
                ah[mf][3] = *(const uint32_t*)&As_hi[r + 8][fc + 8];
                al[mf][0] = *(const uint32_t*)&As_lo[r][fc];
                al[mf][1] = *(const uint32_t*)&As_lo[r + 8][fc];
                al[mf][2] = *(const uint32_t*)&As_lo[r][fc + 8];
                al[mf][3] = *(const uint32_t*)&As_lo[r + 8][fc + 8];
            }
#pragma unroll
            for (int nf = 0; nf < 8; nf++) {
                int n = warp_n + nf * 8 + fr;
                uint32_t bh0 = *(const uint32_t*)&Bs_hi[n][fc];
                uint32_t bh1 = *(const uint32_t*)&Bs_hi[n][fc + 8];
                uint32_t bl0 = *(const uint32_t*)&Bs_lo[n][fc];
                uint32_t bl1 = *(const uint32_t*)&Bs_lo[n][fc + 8];
#pragma unroll
                for (int mf = 0; mf < 2; mf++) {
                    mma16816(acc[mf][nf], ah[mf][0], ah[mf][1], ah[mf][2], ah[mf][3], bh0, bh1);
                    mma16816(acc[mf][nf], ah[mf][0], ah[mf][1], ah[mf][2], ah[mf][3], bl0, bl1);
                    mma16816(acc[mf][nf], al[mf][0], al[mf][1], al[mf][2], al[mf][3], bh0, bh1);
                }
            }
        }
        __syncthreads();
    }

    const int fr = l >> 2;
    const int quad = l & 3;

#pragma unroll
    for (int mf = 0; mf < 2; mf++) {
        int rl0 = warp_m + mf * 16 + fr;
        int rl1 = rl0 + 8;
        int r0 = block_row + rl0;
        int r1 = block_row + rl1;
        float es0 = 0.f, ed0 = 0.f, es1 = 0.f, ed1 = 0.f;
#pragma unroll
        for (int nf = 0; nf < 8; nf++) {
            int cc = warp_n + nf * 8 + quad * 2;
            float as0 = a1_src[cc], as1 = a1_src[cc + 1];
            float ad0 = a1_dst[cc], ad1 = a1_dst[cc + 1];
            es0 += acc[mf][nf][0] * as0 + acc[mf][nf][1] * as1;
            ed0 += acc[mf][nf][0] * ad0 + acc[mf][nf][1] * ad1;
            es1 += acc[mf][nf][2] * as0 + acc[mf][nf][3] * as1;
            ed1 += acc[mf][nf][2] * ad0 + acc[mf][nf][3] * ad1;
            if (r0 < N_NODES)
                *(float2*)&g_h[(size_t)r0 * F_HID + cc] = make_float2(acc[mf][nf][0], acc[mf][nf][1]);
            if (r1 < N_NODES)
                *(float2*)&g_h[(size_t)r1 * F_HID + cc] = make_float2(acc[mf][nf][2], acc[mf][nf][3]);
        }
#pragma unroll
        for (int o = 1; o <= 2; o <<= 1) {
            es0 += __shfl_xor_sync(0xffffffffu, es0, o);
            ed0 += __shfl_xor_sync(0xffffffffu, ed0, o);
            es1 += __shfl_xor_sync(0xffffffffu, es1, o);
            ed1 += __shfl_xor_sync(0xffffffffu, ed1, o);
        }
        if (quad == 0) {
            es_s[rl0][nhalf] = es0;
            ed_s[rl0][nhalf] = ed0;
            es_s[rl1][nhalf] = es1;
            ed_s[rl1][nhalf] = ed1;
        }
    }
    __syncthreads();
    if (tid < 128) {
        int gr = block_row + tid;
        if (gr < N_NODES) {
            g_es1[gr] = es_s[tid][0] + es_s[tid][1];
            g_ed1[gr] = ed_s[tid][0] + ed_s[tid][1];
        }
    }
}

__device__ __forceinline__ float leaky(float x) { return x > 0.f ? x : 0.2f * x; }

// ---------------- layer-1 aggregation (single-pass softmax) + h2/e2 epilogue ----------------
__global__ __launch_bounds__(256) void agg1_k(const float* __restrict__ Wmu,
                                              const float* __restrict__ amus,
                                              const float* __restrict__ amud) {
    int warp = (blockIdx.x * blockDim.x + threadIdx.x) >> 5;
    int lane = threadIdx.x & 31;
    if (warp >= N_NODES) return;
    int v = warp;
    int beg = g_off[v], end = g_off[v + 1];
    float h2_0 = 0.f, h2_1 = 0.f;
    if (beg < end) {
        float edv = g_ed1[v];
        float a0 = 0.f, a1 = 0.f, a2 = 0.f, a3 = 0.f, d = 0.f;
        int j = beg;
        for (; j + 4 <= end; j += 4) {
            int s0 = g_csr_src[j];
            int s1 = g_csr_src[j + 1];
            int s2 = g_csr_src[j + 2];
            int s3 = g_csr_src[j + 3];
            float w0 = expf(leaky(g_es1[s0] + edv));
            float w1 = expf(leaky(g_es1[s1] + edv));
            float w2 = expf(leaky(g_es1[s2] + edv));
            float w3 = expf(leaky(g_es1[s3] + edv));
            const float* hp0 = g_h + (size_t)s0 * F_HID;
            const float* hp1 = g_h + (size_t)s1 * F_HID;
            const float* hp2 = g_h + (size_t)s2 * F_HID;
            const float* hp3 = g_h + (size_t)s3 * F_HID;
            float x00 = hp0[lane], x01 = hp0[lane + 32], x02 = hp0[lane + 64], x03 = hp0[lane + 96];
            float x10 = hp1[lane], x11 = hp1[lane + 32], x12 = hp1[lane + 64], x13 = hp1[lane + 96];
            float x20 = hp2[lane], x21 = hp2[lane + 32], x22 = hp2[lane + 64], x23 = hp2[lane + 96];
            float x30 = hp3[lane], x31 = hp3[lane + 32], x32 = hp3[lane + 64], x33 = hp3[lane + 96];
            d += (w0 + w1) + (w2 + w3);
            a0 += w0 * x00 + w1 * x10 + w2 * x20 + w3 * x30;
            a1 += w0 * x01 + w1 * x11 + w2 * x21 + w3 * x31;
            a2 += w0 * x02 + w1 * x12 + w2 * x22 + w3 * x32;
            a3 += w0 * x03 + w1 * x13 + w2 * x23 + w3 * x33;
        }
        for (; j < end; j++) {
            int s = g_csr_src[j];
            float wgt = expf(leaky(g_es1[s] + edv));
            const float* hp = g_h + (size_t)s * F_HID;
            d += wgt;
            a0 += wgt * hp[lane];
            a1 += wgt * hp[lane + 32];
            a2 += wgt * hp[lane + 64];
            a3 += wgt * hp[lane + 96];
        }
        float inv = 1.f / fmaxf(d, 1e-16f);
        a0 = fmaxf(a0 * inv, 0.f);
        a1 = fmaxf(a1 * inv, 0.f);
        a2 = fmaxf(a2 * inv, 0.f);
        a3 = fmaxf(a3 * inv, 0.f);
        int f0 = lane, f1 = lane + 32, f2 = lane + 64, f3 = lane + 96;
        h2_0 = a0 * Wmu[f0 * 2]     + a1 * Wmu[f1 * 2]     + a2 * Wmu[f2 * 2]     + a3 * Wmu[f3 * 2];
        h2_1 = a0 * Wmu[f0 * 2 + 1] + a1 * Wmu[f1 * 2 + 1] + a2 * Wmu[f2 * 2 + 1] + a3 * Wmu[f3 * 2 + 1];
#pragma unroll
        for (int o = 16; o; o >>= 1) {
            h2_0 += __shfl_xor_sync(0xffffffffu, h2_0, o);
            h2_1 += __shfl_xor_sync(0xffffffffu, h2_1, o);
        }
    }
    if (lane == 0) {
        g_h2[2 * v] = h2_0;
        g_h2[2 * v + 1] = h2_1;
        g_es2[v] = h2_0 * amus[0] + h2_1 * amus[1];
        g_ed2[v] = h2_0 * amud[0] + h2_1 * amud[1];
    }
}

// ---------------- layer-2 aggregation + sampled-softmax logits (fused, single-pass) ----------------
__global__ __launch_bounds__(256) void agg2_logits_k(const int* __restrict__ input_y,
                                                     const int* __restrict__ sample_ids,
                                                     const float* __restrict__ ssw,
                                                     const float* __restrict__ ssb,
                                                     float* __restrict__ out,
                                                     float* __restrict__ mu_out) {
    __shared__ float sw0[N_SAMP], sw1[N_SAMP], sb[N_SAMP];
    for (int i = threadIdx.x; i < N_SAMP; i += blockDim.x) {
        int sid = sample_ids[i];
        sw0[i] = ssw[2 * sid];
        sw1[i] = ssw[2 * sid + 1];
        sb[i] = ssb[sid];
    }
    __syncthreads();

    int warp = (blockIdx.x * blockDim.x + threadIdx.x) >> 5;
    int lane = threadIdx.x & 31;
    if (warp >= N_NODES) return;
    int v = warp;
    int beg = g_off[v], end = g_off[v + 1];
    float mu0 = 0.f, mu1 = 0.f;
    if (beg < end) {
        float edv = g_ed2[v];
        float d = 0.f, a0 = 0.f, a1 = 0.f;
        for (int j = beg + lane; j < end; j += 32) {
            int s = g_csr_src[j];
            float wgt = expf(leaky(g_es2[s] + edv));
            float2 hv = *(const float2*)&g_h2[2 * s];
            d += wgt;
            a0 += wgt * hv.x;
            a1 += wgt * hv.y;
        }
#pragma unroll
        for (int o = 16; o; o >>= 1) {
            d  += __shfl_xor_sync(0xffffffffu, d, o);
            a0 += __shfl_xor_sync(0xffffffffu, a0, o);
            a1 += __shfl_xor_sync(0xffffffffu, a1, o);
        }
        float inv = 1.f / fmaxf(d, 1e-16f);
        mu0 = a0 * inv;
        mu1 = a1 * inv;
    }
    float* row = out + (size_t)v * (N_SAMP + 1);
    if (lane == 0) {
        mu_out[2 * v] = mu0;
        mu_out[2 * v + 1] = mu1;
        int y = input_y[v];
        float tl = mu0 * ssw[2 * y] + mu1 * ssw[2 * y + 1] + ssb[y];
        __stcs(&row[0], tl);
    }
    for (int c = lane + 1; c <= N_SAMP; c += 32) {
        int s = c - 1;
        __stcs(&row[c], mu0 * sw0[s] + mu1 * sw1[s] + sb[s]);
    }
}

// ---------------- launch ----------------
extern "C" void kernel_launch(void* const* d_in, const int* in_sizes, int n_in,
                              void* d_out, int out_size) {
    const float* X         = (const float*)d_in[0];
    const int*   input_y   = (const int*)d_in[2];
    const int*   edge_idx  = (const int*)d_in[3];
    const int*   sample_ids= (const int*)d_in[4];
    const float* W1        = (const float*)d_in[5];
    const float* a1_src    = (const float*)d_in[6];
    const float* a1_dst    = (const float*)d_in[7];
    const float* W_mu      = (const float*)d_in[8];
    const float* amu_src   = (const float*)d_in[9];
    const float* amu_dst   = (const float*)d_in[10];
    const float* ss_weight = (const float*)d_in[14];
    const float* ss_bias   = (const float*)d_in[15];
    float* out = (float*)d_out;

    float* mu_out = out + (size_t)N_NODES * (N_SAMP + 1);

    // CSR build + W1 split
    zero_split_k<<<(N_NODES + 255) / 256, 256>>>(W1);
    hist_k<<<(N_EDGES + 255) / 256, 256>>>(edge_idx);
    bsum_k<<<SCAN_NB, SCAN_B>>>();
    scan_bsums_k<<<1, 512>>>();
    write_off_k<<<SCAN_NB, SCAN_B>>>();
    fill_k<<<(N_EDGES + 255) / 256, 256>>>(edge_idx);

    // tensor-core GEMM with fused attention-dot epilogue
    gemm_mma_k<<<(N_NODES + 127) / 128, 256>>>(X, a1_src, a1_dst);

    int warp_blocks = (N_NODES * 32 + 255) / 256;
    agg1_k<<<warp_blocks, 256>>>(W_mu, amu_src, amu_dst);
    agg2_logits_k<<<warp_blocks, 256>>>(input_y, sample_ids, ss_weight, ss_bias, out, mu_out);
}

// round 6
// speedup vs baseline: 2.1870x; 1.0727x over previous
#include <cuda_runtime.h>
#include <cuda_bf16.h>
#include <math.h>
#include <stdint.h>

#define N_NODES 100000
#define N_EDGES 1600000
#define F_IN 256
#define F_HID 128
#define VOCAB 100000
#define N_SAMP 512

#define SCAN_B 256
#define SCAN_NB ((N_NODES + SCAN_B - 1) / SCAN_B)   // 391

// ---------------- scratch (static __device__ — no allocations) ----------------
__device__ float g_h[(size_t)N_NODES * F_HID];     // 51.2 MB, fits L2
__device__ float g_es1[N_NODES];
__device__ float g_ed1[N_NODES];
__device__ int   g_counts[N_NODES];
__device__ int   g_off[N_NODES + 1];
__device__ int   g_cursor[N_NODES];
__device__ int   g_csr_src[N_EDGES];
__device__ float g_h2[2 * N_NODES];
__device__ float g_es2[N_NODES];
__device__ float g_ed2[N_NODES];
__device__ int   g_bsum[SCAN_NB];
__device__ int   g_boff[SCAN_NB];
__device__ __nv_bfloat16 g_Bt_hi[F_HID * F_IN];
__device__ __nv_bfloat16 g_Bt_lo[F_HID * F_IN];

// ---------------- CSR build + W1 split (merged zero/split) ----------------
__global__ void zero_split_k(const float* __restrict__ W1) {
    int i = blockIdx.x * blockDim.x + threadIdx.x;
    if (i < N_NODES) g_counts[i] = 0;
    if (i < F_HID * F_IN) {
        int n = i / F_IN;
        int k = i % F_IN;
        float w = W1[(size_t)k * F_HID + n];
        __nv_bfloat16 hi = __float2bfloat16(w);
        float r = w - __bfloat162float(hi);
        g_Bt_hi[i] = hi;
        g_Bt_lo[i] = __float2bfloat16(r);
    }
}

__global__ void hist_k(const int* __restrict__ edge_index) {
    int e = blockIdx.x * blockDim.x + threadIdx.x;
    if (e < N_EDGES) {
        int dst = edge_index[N_EDGES + e];
        atomicAdd(&g_counts[dst], 1);
    }
}

__global__ __launch_bounds__(SCAN_B) void bsum_k() {
    int i = blockIdx.x * SCAN_B + threadIdx.x;
    int c = (i < N_NODES) ? g_counts[i] : 0;
#pragma unroll
    for (int o = 16; o; o >>= 1) c += __shfl_xor_sync(0xffffffffu, c, o);
    __shared__ int ws[SCAN_B / 32];
    if ((threadIdx.x & 31) == 0) ws[threadIdx.x >> 5] = c;
    __syncthreads();
    if (threadIdx.x < SCAN_B / 32) {
        int v = ws[threadIdx.x];
#pragma unroll
        for (int o = SCAN_B / 64; o; o >>= 1) v += __shfl_xor_sync(0xffffffffu, v, o);
        if (threadIdx.x == 0) g_bsum[blockIdx.x] = v;
    }
}

__global__ __launch_bounds__(512) void scan_bsums_k() {
    __shared__ int s[512];
    int t = threadIdx.x;
    int v = (t < SCAN_NB) ? g_bsum[t] : 0;
    s[t] = v;
    __syncthreads();
    for (int d = 1; d < 512; d <<= 1) {
        int x = 0;
        if (t >= d) x = s[t - d];
        __syncthreads();
        s[t] += x;
        __syncthreads();
    }
    if (t < SCAN_NB) g_boff[t] = s[t] - v;
    if (t == 511) g_off[N_NODES] = s[SCAN_NB - 1];
}

__global__ __launch_bounds__(SCAN_B) void write_off_k() {
    int i = blockIdx.x * SCAN_B + threadIdx.x;
    int lane = threadIdx.x & 31;
    int wid = threadIdx.x >> 5;
    int c = (i < N_NODES) ? g_counts[i] : 0;
    int inc = c;
#pragma unroll
    for (int d = 1; d < 32; d <<= 1) {
        int x = __shfl_up_sync(0xffffffffu, inc, d);
        if (lane >= d) inc += x;
    }
    __shared__ int wsum[SCAN_B / 32];
    if (lane == 31) wsum[wid] = inc;
    __syncthreads();
    if (threadIdx.x == 0) {
        int run = 0;
#pragma unroll
        for (int wv = 0; wv < SCAN_B / 32; wv++) {
            int x = wsum[wv];
            wsum[wv] = run;
            run += x;
        }
    }
    __syncthreads();
    int off = g_boff[blockIdx.x] + wsum[wid] + inc - c;
    if (i < N_NODES) {
        g_off[i] = off;
        g_cursor[i] = off;
    }
}

__global__ void fill_k(const int* __restrict__ edge_index) {
    int e = blockIdx.x * blockDim.x + threadIdx.x;
    if (e < N_EDGES) {
        int src = edge_index[e];
        int dst = edge_index[N_EDGES + e];
        int pos = atomicAdd(&g_cursor[dst], 1);
        g_csr_src[pos] = src;
    }
}

// ---------------- tensor-core GEMM + fused attention-dot epilogue ----------------
#define SMEM_STRIDE 40

__device__ __forceinline__ void mma16816(float* d,
                                         uint32_t a0, uint32_t a1, uint32_t a2, uint32_t a3,
                                         uint32_t b0, uint32_t b1) {
    asm volatile(
        "mma.sync.aligned.m16n8k16.row.col.f32.bf16.bf16.f32 "
        "{%0,%1,%2,%3}, {%4,%5,%6,%7}, {%8,%9}, {%0,%1,%2,%3};\n"
        : "+f"(d[0]), "+f"(d[1]), "+f"(d[2]), "+f"(d[3])
        : "r"(a0), "r"(a1), "r"(a2), "r"(a3), "r"(b0), "r"(b1));
}

__global__ __launch_bounds__(256) void gemm_mma_k(const float* __restrict__ A,
                                                  const float* __restrict__ a1_src,
                                                  const float* __restrict__ a1_dst) {
    __shared__ __nv_bfloat16 As_hi[128][SMEM_STRIDE];
    __shared__ __nv_bfloat16 As_lo[128][SMEM_STRIDE];
    __shared__ __nv_bfloat16 Bs_hi[128][SMEM_STRIDE];
    __shared__ __nv_bfloat16 Bs_lo[128][SMEM_STRIDE];
    __shared__ float es_s[128][2], ed_s[128][2];

    const int tid = threadIdx.x;
    const int block_row = blockIdx.x * 128;
    const int w = tid >> 5, l = tid & 31;
    const int warp_m = (w >> 1) * 32;
    const int warp_n = (w & 1) * 64;
    const int nhalf = w & 1;

    float acc[2][8][4];
#pragma unroll
    for (int i = 0; i < 2; i++)
#pragma unroll
        for (int j = 0; j < 8; j++)
#pragma unroll
            for (int q = 0; q < 4; q++) acc[i][j][q] = 0.f;

    const int ar = tid >> 1;
    const int ac = (tid & 1) * 16;

    for (int k0 = 0; k0 < F_IN; k0 += 32) {
        {
            int gr = block_row + ar;
#pragma unroll
            for (int j = 0; j < 4; j++) {
                float4 v = make_float4(0.f, 0.f, 0.f, 0.f);
                if (gr < N_NODES)
                    v = *(const float4*)(A + (size_t)gr * F_IN + k0 + ac + j * 4);
                float xs[4] = {v.x, v.y, v.z, v.w};
                __nv_bfloat16 hi[4], lo[4];
#pragma unroll
                for (int c = 0; c < 4; c++) {
                    hi[c] = __float2bfloat16(xs[c]);
                    lo[c] = __float2bfloat16(xs[c] - __bfloat162float(hi[c]));
                }
                __nv_bfloat162* ph = (__nv_bfloat162*)&As_hi[ar][ac + j * 4];
                __nv_bfloat162* pl = (__nv_bfloat162*)&As_lo[ar][ac + j * 4];
                ph[0] = __nv_bfloat162(hi[0], hi[1]);
                ph[1] = __nv_bfloat162(hi[2], hi[3]);
                pl[0] = __nv_bfloat162(lo[0], lo[1]);
                pl[1] = __nv_bfloat162(lo[2], lo[3]);
            }
        }
        {
            const __nv_bfloat16* bh = g_Bt_hi + (size_t)ar * F_IN + k0 + ac;
            const __nv_bfloat16* bl = g_Bt_lo + (size_t)ar * F_IN + k0 + ac;
            *(uint4*)&Bs_hi[ar][ac] = *(const uint4*)bh;
            *(uint4*)&Bs_hi[ar][ac + 8] = *(const uint4*)(bh + 8);
            *(uint4*)&Bs_lo[ar][ac] = *(const uint4*)bl;
            *(uint4*)&Bs_lo[ar][ac + 8] = *(const uint4*)(bl + 8);
        }
        __syncthreads();

#pragma unroll
        for (int ks = 0; ks < 32; ks += 16) {
            const int fr = l >> 2;
            const int fc = ks + (l & 3) * 2;
            uint32_t ah[2][4], al[2][4];
#pragma unroll
            for (int mf = 0; mf < 2; mf++) {
                int r = warp_m + mf * 16 + fr;
                ah[mf][0] = *(const uint32_t*)&As_hi[r][fc];
                ah[mf][1] = *(const uint32_t*)&As_hi[r + 8][fc];
                ah[mf][2] = *(const uint32_t*)&As_hi[r][fc + 8];
                ah[mf][3] = *(const uint32_t*)&As_hi[r + 8][fc + 8];
                al[mf][0] = *(const uint32_t*)&As_lo[r][fc];
                al[mf][1] = *(const uint32_t*)&As_lo[r + 8][fc];
                al[mf][2] = *(const uint32_t*)&As_lo[r][fc + 8];
                al[mf][3] = *(const uint32_t*)&As_lo[r + 8][fc + 8];
            }
#pragma unroll
            for (int nf = 0; nf < 8; nf++) {
                int n = warp_n + nf * 8 + fr;
                uint32_t bh0 = *(const uint32_t*)&Bs_hi[n][fc];
                uint32_t bh1 = *(const uint32_t*)&Bs_hi[n][fc + 8];
                uint32_t bl0 = *(const uint32_t*)&Bs_lo[n][fc];
                uint32_t bl1 = *(const uint32_t*)&Bs_lo[n][fc + 8];
#pragma unroll
                for (int mf = 0; mf < 2; mf++) {
                    mma16816(acc[mf][nf], ah[mf][0], ah[mf][1], ah[mf][2], ah[mf][3], bh0, bh1);
                    mma16816(acc[mf][nf], ah[mf][0], ah[mf][1], ah[mf][2], ah[mf][3], bl0, bl1);
                    mma16816(acc[mf][nf], al[mf][0], al[mf][1], al[mf][2], al[mf][3], bh0, bh1);
                }
            }
        }
        __syncthreads();
    }

    const int fr = l >> 2;
    const int quad = l & 3;

#pragma unroll
    for (int mf = 0; mf < 2; mf++) {
        int rl0 = warp_m + mf * 16 + fr;
        int rl1 = rl0 + 8;
        int r0 = block_row + rl0;
        int r1 = block_row + rl1;
        float es0 = 0.f, ed0 = 0.f, es1 = 0.f, ed1 = 0.f;
#pragma unroll
        for (int nf = 0; nf < 8; nf++) {
            int cc = warp_n + nf * 8 + quad * 2;
            float as0 = a1_src[cc], as1 = a1_src[cc + 1];
            float ad0 = a1_dst[cc], ad1 = a1_dst[cc + 1];
            es0 += acc[mf][nf][0] * as0 + acc[mf][nf][1] * as1;
            ed0 += acc[mf][nf][0] * ad0 + acc[mf][nf][1] * ad1;
            es1 += acc[mf][nf][2] * as0 + acc[mf][nf][3] * as1;
            ed1 += acc[mf][nf][2] * ad0 + acc[mf][nf][3] * ad1;
            if (r0 < N_NODES)
                *(float2*)&g_h[(size_t)r0 * F_HID + cc] = make_float2(acc[mf][nf][0], acc[mf][nf][1]);
            if (r1 < N_NODES)
                *(float2*)&g_h[(size_t)r1 * F_HID + cc] = make_float2(acc[mf][nf][2], acc[mf][nf][3]);
        }
#pragma unroll
        for (int o = 1; o <= 2; o <<= 1) {
            es0 += __shfl_xor_sync(0xffffffffu, es0, o);
            ed0 += __shfl_xor_sync(0xffffffffu, ed0, o);
            es1 += __shfl_xor_sync(0xffffffffu, es1, o);
            ed1 += __shfl_xor_sync(0xffffffffu, ed1, o);
        }
        if (quad == 0) {
            es_s[rl0][nhalf] = es0;
            ed_s[rl0][nhalf] = ed0;
            es_s[rl1][nhalf] = es1;
            ed_s[rl1][nhalf] = ed1;
        }
    }
    __syncthreads();
    if (tid < 128) {
        int gr = block_row + tid;
        if (gr < N_NODES) {
            g_es1[gr] = es_s[tid][0] + es_s[tid][1];
            g_ed1[gr] = ed_s[tid][0] + ed_s[tid][1];
        }
    }
}

__device__ __forceinline__ float leaky(float x) { return x > 0.f ? x : 0.2f * x; }

// ---------------- layer-1 aggregation (single-pass softmax) + h2/e2 epilogue ----------------
__global__ __launch_bounds__(256) void agg1_k(const float* __restrict__ Wmu,
                                              const float* __restrict__ amus,
                                              const float* __restrict__ amud) {
    int warp = (blockIdx.x * blockDim.x + threadIdx.x) >> 5;
    int lane = threadIdx.x & 31;
    if (warp >= N_NODES) return;
    int v = warp;
    int beg = g_off[v], end = g_off[v + 1];
    float h2_0 = 0.f, h2_1 = 0.f;
    if (beg < end) {
        float edv = g_ed1[v];
        float a0 = 0.f, a1 = 0.f, a2 = 0.f, a3 = 0.f, d = 0.f;
        int j = beg;
        for (; j + 4 <= end; j += 4) {
            int s0 = g_csr_src[j];
            int s1 = g_csr_src[j + 1];
            int s2 = g_csr_src[j + 2];
            int s3 = g_csr_src[j + 3];
            float w0 = expf(leaky(g_es1[s0] + edv));
            float w1 = expf(leaky(g_es1[s1] + edv));
            float w2 = expf(leaky(g_es1[s2] + edv));
            float w3 = expf(leaky(g_es1[s3] + edv));
            const float* hp0 = g_h + (size_t)s0 * F_HID;
            const float* hp1 = g_h + (size_t)s1 * F_HID;
            const float* hp2 = g_h + (size_t)s2 * F_HID;
            const float* hp3 = g_h + (size_t)s3 * F_HID;
            float x00 = hp0[lane], x01 = hp0[lane + 32], x02 = hp0[lane + 64], x03 = hp0[lane + 96];
            float x10 = hp1[lane], x11 = hp1[lane + 32], x12 = hp1[lane + 64], x13 = hp1[lane + 96];
            float x20 = hp2[lane], x21 = hp2[lane + 32], x22 = hp2[lane + 64], x23 = hp2[lane + 96];
            float x30 = hp3[lane], x31 = hp3[lane + 32], x32 = hp3[lane + 64], x33 = hp3[lane + 96];
            d += (w0 + w1) + (w2 + w3);
            a0 += w0 * x00 + w1 * x10 + w2 * x20 + w3 * x30;
            a1 += w0 * x01 + w1 * x11 + w2 * x21 + w3 * x31;
            a2 += w0 * x02 + w1 * x12 + w2 * x22 + w3 * x32;
            a3 += w0 * x03 + w1 * x13 + w2 * x23 + w3 * x33;
        }
        for (; j < end; j++) {
            int s = g_csr_src[j];
            float wgt = expf(leaky(g_es1[s] + edv));
            const float* hp = g_h + (size_t)s * F_HID;
            d += wgt;
            a0 += wgt * hp[lane];
            a1 += wgt * hp[lane + 32];
            a2 += wgt * hp[lane + 64];
            a3 += wgt * hp[lane + 96];
        }
        float inv = 1.f / fmaxf(d, 1e-16f);
        a0 = fmaxf(a0 * inv, 0.f);
        a1 = fmaxf(a1 * inv, 0.f);
        a2 = fmaxf(a2 * inv, 0.f);
        a3 = fmaxf(a3 * inv, 0.f);
        int f0 = lane, f1 = lane + 32, f2 = lane + 64, f3 = lane + 96;
        h2_0 = a0 * Wmu[f0 * 2]     + a1 * Wmu[f1 * 2]     + a2 * Wmu[f2 * 2]     + a3 * Wmu[f3 * 2];
        h2_1 = a0 * Wmu[f0 * 2 + 1] + a1 * Wmu[f1 * 2 + 1] + a2 * Wmu[f2 * 2 + 1] + a3 * Wmu[f3 * 2 + 1];
#pragma unroll
        for (int o = 16; o; o >>= 1) {
            h2_0 += __shfl_xor_sync(0xffffffffu, h2_0, o);
            h2_1 += __shfl_xor_sync(0xffffffffu, h2_1, o);
        }
    }
    if (lane == 0) {
        g_h2[2 * v] = h2_0;
        g_h2[2 * v + 1] = h2_1;
        g_es2[v] = h2_0 * amus[0] + h2_1 * amus[1];
        g_ed2[v] = h2_0 * amud[0] + h2_1 * amud[1];
    }
}

// ---------------- layer-2 aggregation + sampled-softmax logits (fused, single-pass) ----------------
__global__ __launch_bounds__(256) void agg2_logits_k(const int* __restrict__ input_y,
                                                     const int* __restrict__ sample_ids,
                                                     const float* __restrict__ ssw,
                                                     const float* __restrict__ ssb,
                                                     float* __restrict__ out,
                                                     float* __restrict__ mu_out) {
    __shared__ float sw0[N_SAMP], sw1[N_SAMP], sb[N_SAMP];
    for (int i = threadIdx.x; i < N_SAMP; i += blockDim.x) {
        int sid = sample_ids[i];
        sw0[i] = ssw[2 * sid];
        sw1[i] = ssw[2 * sid + 1];
        sb[i] = ssb[sid];
    }
    __syncthreads();

    int warp = (blockIdx.x * blockDim.x + threadIdx.x) >> 5;
    int lane = threadIdx.x & 31;
    if (warp >= N_NODES) return;
    int v = warp;
    int beg = g_off[v], end = g_off[v + 1];
    float mu0 = 0.f, mu1 = 0.f;
    if (beg < end) {
        float edv = g_ed2[v];
        float d = 0.f, a0 = 0.f, a1 = 0.f;
        for (int j = beg + lane; j < end; j += 32) {
            int s = g_csr_src[j];
            float wgt = expf(leaky(g_es2[s] + edv));
            float2 hv = *(const float2*)&g_h2[2 * s];
            d += wgt;
            a0 += wgt * hv.x;
            a1 += wgt * hv.y;
        }
#pragma unroll
        for (int o = 16; o; o >>= 1) {
            d  += __shfl_xor_sync(0xffffffffu, d, o);
            a0 += __shfl_xor_sync(0xffffffffu, a0, o);
            a1 += __shfl_xor_sync(0xffffffffu, a1, o);
        }
        float inv = 1.f / fmaxf(d, 1e-16f);
        mu0 = a0 * inv;
        mu1 = a1 * inv;
    }
    float* row = out + (size_t)v * (N_SAMP + 1);
    if (lane == 0) {
        mu_out[2 * v] = mu0;
        mu_out[2 * v + 1] = mu1;
        int y = input_y[v];
        float tl = mu0 * ssw[2 * y] + mu1 * ssw[2 * y + 1] + ssb[y];
        __stcs(&row[0], tl);
    }
    for (int c = lane + 1; c <= N_SAMP; c += 32) {
        int s = c - 1;
        __stcs(&row[c], mu0 * sw0[s] + mu1 * sw1[s] + sb[s]);
    }
}

// ---------------- launch (fork/join: CSR chain overlaps GEMM) ----------------
static cudaStream_t g_s2 = nullptr;
static cudaEvent_t g_ev_fork = nullptr;
static cudaEvent_t g_ev_join = nullptr;

extern "C" void kernel_launch(void* const* d_in, const int* in_sizes, int n_in,
                              void* d_out, int out_size) {
    const float* X         = (const float*)d_in[0];
    const int*   input_y   = (const int*)d_in[2];
    const int*   edge_idx  = (const int*)d_in[3];
    const int*   sample_ids= (const int*)d_in[4];
    const float* W1        = (const float*)d_in[5];
    const float* a1_src    = (const float*)d_in[6];
    const float* a1_dst    = (const float*)d_in[7];
    const float* W_mu      = (const float*)d_in[8];
    const float* amu_src   = (const float*)d_in[9];
    const float* amu_dst   = (const float*)d_in[10];
    const float* ss_weight = (const float*)d_in[14];
    const float* ss_bias   = (const float*)d_in[15];
    float* out = (float*)d_out;

    float* mu_out = out + (size_t)N_NODES * (N_SAMP + 1);

    if (g_s2 == nullptr) {
        cudaStreamCreateWithFlags(&g_s2, cudaStreamNonBlocking);
        cudaEventCreateWithFlags(&g_ev_fork, cudaEventDisableTiming);
        cudaEventCreateWithFlags(&g_ev_join, cudaEventDisableTiming);
    }

    // counts zero + W1 split (needed by both branches)
    zero_split_k<<<(N_NODES + 255) / 256, 256>>>(W1);

    // fork: CSR chain on side stream
    cudaEventRecord(g_ev_fork, 0);
    cudaStreamWaitEvent(g_s2, g_ev_fork, 0);
    hist_k<<<(N_EDGES + 255) / 256, 256, 0, g_s2>>>(edge_idx);
    bsum_k<<<SCAN_NB, SCAN_B, 0, g_s2>>>();
    scan_bsums_k<<<1, 512, 0, g_s2>>>();
    write_off_k<<<SCAN_NB, SCAN_B, 0, g_s2>>>();
    fill_k<<<(N_EDGES + 255) / 256, 256, 0, g_s2>>>(edge_idx);
    cudaEventRecord(g_ev_join, g_s2);

    // main stream: tensor-core GEMM with fused attention-dot epilogue (concurrent)
    gemm_mma_k<<<(N_NODES + 127) / 128, 256>>>(X, a1_src, a1_dst);

    // join, then aggregation phases
    cudaStreamWaitEvent(0, g_ev_join, 0);
    int warp_blocks = (N_NODES * 32 + 255) / 256;
    agg1_k<<<warp_blocks, 256>>>(W_mu, amu_src, amu_dst);
    agg2_logits_k<<<warp_blocks, 256>>>(input_y, sample_ids, ss_weight, ss_bias, out, mu_out);
}

// round 7
// speedup vs baseline: 2.2465x; 1.0272x over previous
#include <cuda_runtime.h>
#include <cuda_bf16.h>
#include <cuda_fp16.h>
#include <math.h>
#include <stdint.h>

#define N_NODES 100000
#define N_EDGES 1600000
#define F_IN 256
#define F_HID 128
#define VOCAB 100000
#define N_SAMP 512

#define SCAN_B 256
#define SCAN_NB ((N_NODES + SCAN_B - 1) / SCAN_B)   // 391

// ---------------- scratch (static __device__ — no allocations) ----------------
__device__ uint32_t g_h16[(size_t)N_NODES * (F_HID / 2)];   // h as half2 pairs, 25.6 MB
__device__ float g_es1[N_NODES];
__device__ float g_ed1[N_NODES];
__device__ int   g_counts[N_NODES];
__device__ int   g_off[N_NODES + 1];
__device__ int   g_cursor[N_NODES];
__device__ int   g_csr_src[N_EDGES];
__device__ float g_h2[2 * N_NODES];
__device__ float g_es2[N_NODES];
__device__ float g_ed2[N_NODES];
__device__ int   g_bsum[SCAN_NB];
__device__ int   g_boff[SCAN_NB];
__device__ __nv_bfloat16 g_Bt_hi[F_HID * F_IN];
__device__ __nv_bfloat16 g_Bt_lo[F_HID * F_IN];

// ---------------- CSR build + W1 split (merged zero/split) ----------------
__global__ void zero_split_k(const float* __restrict__ W1) {
    int i = blockIdx.x * blockDim.x + threadIdx.x;
    if (i < N_NODES) g_counts[i] = 0;
    if (i < F_HID * F_IN) {
        int n = i / F_IN;
        int k = i % F_IN;
        float w = W1[(size_t)k * F_HID + n];
        __nv_bfloat16 hi = __float2bfloat16(w);
        float r = w - __bfloat162float(hi);
        g_Bt_hi[i] = hi;
        g_Bt_lo[i] = __float2bfloat16(r);
    }
}

__global__ void hist_k(const int* __restrict__ edge_index) {
    int e = blockIdx.x * blockDim.x + threadIdx.x;
    if (e < N_EDGES) {
        int dst = edge_index[N_EDGES + e];
        atomicAdd(&g_counts[dst], 1);
    }
}

__global__ __launch_bounds__(SCAN_B) void bsum_k() {
    int i = blockIdx.x * SCAN_B + threadIdx.x;
    int c = (i < N_NODES) ? g_counts[i] : 0;
#pragma unroll
    for (int o = 16; o; o >>= 1) c += __shfl_xor_sync(0xffffffffu, c, o);
    __shared__ int ws[SCAN_B / 32];
    if ((threadIdx.x & 31) == 0) ws[threadIdx.x >> 5] = c;
    __syncthreads();
    if (threadIdx.x < SCAN_B / 32) {
        int v = ws[threadIdx.x];
#pragma unroll
        for (int o = SCAN_B / 64; o; o >>= 1) v += __shfl_xor_sync(0xffffffffu, v, o);
        if (threadIdx.x == 0) g_bsum[blockIdx.x] = v;
    }
}

__global__ __launch_bounds__(512) void scan_bsums_k() {
    __shared__ int s[512];
    int t = threadIdx.x;
    int v = (t < SCAN_NB) ? g_bsum[t] : 0;
    s[t] = v;
    __syncthreads();
    for (int d = 1; d < 512; d <<= 1) {
        int x = 0;
        if (t >= d) x = s[t - d];
        __syncthreads();
        s[t] += x;
        __syncthreads();
    }
    if (t < SCAN_NB) g_boff[t] = s[t] - v;
    if (t == 511) g_off[N_NODES] = s[SCAN_NB - 1];
}

__global__ __launch_bounds__(SCAN_B) void write_off_k() {
    int i = blockIdx.x * SCAN_B + threadIdx.x;
    int lane = threadIdx.x & 31;
    int wid = threadIdx.x >> 5;
    int c = (i < N_NODES) ? g_counts[i] : 0;
    int inc = c;
#pragma unroll
    for (int d = 1; d < 32; d <<= 1) {
        int x = __shfl_up_sync(0xffffffffu, inc, d);
        if (lane >= d) inc += x;
    }
    __shared__ int wsum[SCAN_B / 32];
    if (lane == 31) wsum[wid] = inc;
    __syncthreads();
    if (threadIdx.x == 0) {
        int run = 0;
#pragma unroll
        for (int wv = 0; wv < SCAN_B / 32; wv++) {
            int x = wsum[wv];
            wsum[wv] = run;
            run += x;
        }
    }
    __syncthreads();
    int off = g_boff[blockIdx.x] + wsum[wid] + inc - c;
    if (i < N_NODES) {
        g_off[i] = off;
        g_cursor[i] = off;
    }
}

__global__ void fill_k(const int* __restrict__ edge_index) {
    int e = blockIdx.x * blockDim.x + threadIdx.x;
    if (e < N_EDGES) {
        int src = edge_index[e];
        int dst = edge_index[N_EDGES + e];
        int pos = atomicAdd(&g_cursor[dst], 1);
        g_csr_src[pos] = src;
    }
}

// ---------------- tensor-core GEMM + fused attention-dot epilogue (h -> fp16) ----------------
#define SMEM_STRIDE 40

__device__ __forceinline__ void mma16816(float* d,
                                         uint32_t a0, uint32_t a1, uint32_t a2, uint32_t a3,
                                         uint32_t b0, uint32_t b1) {
    asm volatile(
        "mma.sync.aligned.m16n8k16.row.col.f32.bf16.bf16.f32 "
        "{%0,%1,%2,%3}, {%4,%5,%6,%7}, {%8,%9}, {%0,%1,%2,%3};\n"
        : "+f"(d[0]), "+f"(d[1]), "+f"(d[2]), "+f"(d[3])
        : "r"(a0), "r"(a1), "r"(a2), "r"(a3), "r"(b0), "r"(b1));
}

__global__ __launch_bounds__(256) void gemm_mma_k(const float* __restrict__ A,
                                                  const float* __restrict__ a1_src,
                                                  const float* __restrict__ a1_dst) {
    __shared__ __nv_bfloat16 As_hi[128][SMEM_STRIDE];
    __shared__ __nv_bfloat16 As_lo[128][SMEM_STRIDE];
    __shared__ __nv_bfloat16 Bs_hi[128][SMEM_STRIDE];
    __shared__ __nv_bfloat16 Bs_lo[128][SMEM_STRIDE];
    __shared__ float es_s[128][2], ed_s[128][2];

    const int tid = threadIdx.x;
    const int block_row = blockIdx.x * 128;
    const int w = tid >> 5, l = tid & 31;
    const int warp_m = (w >> 1) * 32;
    const int warp_n = (w & 1) * 64;
    const int nhalf = w & 1;

    float acc[2][8][4];
#pragma unroll
    for (int i = 0; i < 2; i++)
#pragma unroll
        for (int j = 0; j < 8; j++)
#pragma unroll
            for (int q = 0; q < 4; q++) acc[i][j][q] = 0.f;

    const int ar = tid >> 1;
    const int ac = (tid & 1) * 16;

    for (int k0 = 0; k0 < F_IN; k0 += 32) {
        {
            int gr = block_row + ar;
#pragma unroll
            for (int j = 0; j < 4; j++) {
                float4 v = make_float4(0.f, 0.f, 0.f, 0.f);
                if (gr < N_NODES)
                    v = *(const float4*)(A + (size_t)gr * F_IN + k0 + ac + j * 4);
                float xs[4] = {v.x, v.y, v.z, v.w};
                __nv_bfloat16 hi[4], lo[4];
#pragma unroll
                for (int c = 0; c < 4; c++) {
                    hi[c] = __float2bfloat16(xs[c]);
                    lo[c] = __float2bfloat16(xs[c] - __bfloat162float(hi[c]));
                }
                __nv_bfloat162* ph = (__nv_bfloat162*)&As_hi[ar][ac + j * 4];
                __nv_bfloat162* pl = (__nv_bfloat162*)&As_lo[ar][ac + j * 4];
                ph[0] = __nv_bfloat162(hi[0], hi[1]);
                ph[1] = __nv_bfloat162(hi[2], hi[3]);
                pl[0] = __nv_bfloat162(lo[0], lo[1]);
                pl[1] = __nv_bfloat162(lo[2], lo[3]);
            }
        }
        {
            const __nv_bfloat16* bh = g_Bt_hi + (size_t)ar * F_IN + k0 + ac;
            const __nv_bfloat16* bl = g_Bt_lo + (size_t)ar * F_IN + k0 + ac;
            *(uint4*)&Bs_hi[ar][ac] = *(const uint4*)bh;
            *(uint4*)&Bs_hi[ar][ac + 8] = *(const uint4*)(bh + 8);
            *(uint4*)&Bs_lo[ar][ac] = *(const uint4*)bl;
            *(uint4*)&Bs_lo[ar][ac + 8] = *(const uint4*)(bl + 8);
        }
        __syncthreads();

#pragma unroll
        for (int ks = 0; ks < 32; ks += 16) {
            const int fr = l >> 2;
            const int fc = ks + (l & 3) * 2;
            uint32_t ah[2][4], al[2][4];
#pragma unroll
            for (int mf = 0; mf < 2; mf++) {
                int r = warp_m + mf * 16 + fr;
                ah[mf][0] = *(const uint32_t*)&As_hi[r][fc];
                ah[mf][1] = *(const uint32_t*)&As_hi[r + 8][fc];
                ah[mf][2] = *(const uint32_t*)&As_hi[r][fc + 8];
                ah[mf][3] = *(const uint32_t*)&As_hi[r + 8][fc + 8];
                al[mf][0] = *(const uint32_t*)&As_lo[r][fc];
                al[mf][1] = *(const uint32_t*)&As_lo[r + 8][fc];
                al[mf][2] = *(const uint32_t*)&As_lo[r][fc + 8];
                al[mf][3] = *(const uint32_t*)&As_lo[r + 8][fc + 8];
            }
#pragma unroll
            for (int nf = 0; nf < 8; nf++) {
                int n = warp_n + nf * 8 + fr;
                uint32_t bh0 = *(const uint32_t*)&Bs_hi[n][fc];
                uint32_t bh1 = *(const uint32_t*)&Bs_hi[n][fc + 8];
                uint32_t bl0 = *(const uint32_t*)&Bs_lo[n][fc];
                uint32_t bl1 = *(const uint32_t*)&Bs_lo[n][fc + 8];
#pragma unroll
                for (int mf = 0; mf < 2; mf++) {
                    mma16816(acc[mf][nf], ah[mf][0], ah[mf][1], ah[mf][2], ah[mf][3], bh0, bh1);
                    mma16816(acc[mf][nf], ah[mf][0], ah[mf][1], ah[mf][2], ah[mf][3], bl0, bl1);
                    mma16816(acc[mf][nf], al[mf][0], al[mf][1], al[mf][2], al[mf][3], bh0, bh1);
                }
            }
        }
        __syncthreads();
    }

    const int fr = l >> 2;
    const int quad = l & 3;

#pragma unroll
    for (int mf = 0; mf < 2; mf++) {
        int rl0 = warp_m + mf * 16 + fr;
        int rl1 = rl0 + 8;
        int r0 = block_row + rl0;
        int r1 = block_row + rl1;
        float es0 = 0.f, ed0 = 0.f, es1 = 0.f, ed1 = 0.f;
#pragma unroll
        for (int nf = 0; nf < 8; nf++) {
            int cc = warp_n + nf * 8 + quad * 2;
            float as0 = a1_src[cc], as1 = a1_src[cc + 1];
            float ad0 = a1_dst[cc], ad1 = a1_dst[cc + 1];
            es0 += acc[mf][nf][0] * as0 + acc[mf][nf][1] * as1;
            ed0 += acc[mf][nf][0] * ad0 + acc[mf][nf][1] * ad1;
            es1 += acc[mf][nf][2] * as0 + acc[mf][nf][3] * as1;
            ed1 += acc[mf][nf][2] * ad0 + acc[mf][nf][3] * ad1;
            // h stored as half2 (feature pair cc, cc+1)
            if (r0 < N_NODES) {
                __half2 hv = __floats2half2_rn(acc[mf][nf][0], acc[mf][nf][1]);
                g_h16[(size_t)r0 * (F_HID / 2) + (cc >> 1)] = *(uint32_t*)&hv;
            }
            if (r1 < N_NODES) {
                __half2 hv = __floats2half2_rn(acc[mf][nf][2], acc[mf][nf][3]);
                g_h16[(size_t)r1 * (F_HID / 2) + (cc >> 1)] = *(uint32_t*)&hv;
            }
        }
#pragma unroll
        for (int o = 1; o <= 2; o <<= 1) {
            es0 += __shfl_xor_sync(0xffffffffu, es0, o);
            ed0 += __shfl_xor_sync(0xffffffffu, ed0, o);
            es1 += __shfl_xor_sync(0xffffffffu, es1, o);
            ed1 += __shfl_xor_sync(0xffffffffu, ed1, o);
        }
        if (quad == 0) {
            es_s[rl0][nhalf] = es0;
            ed_s[rl0][nhalf] = ed0;
            es_s[rl1][nhalf] = es1;
            ed_s[rl1][nhalf] = ed1;
        }
    }
    __syncthreads();
    if (tid < 128) {
        int gr = block_row + tid;
        if (gr < N_NODES) {
            g_es1[gr] = es_s[tid][0] + es_s[tid][1];
            g_ed1[gr] = ed_s[tid][0] + ed_s[tid][1];
        }
    }
}

__device__ __forceinline__ float leaky(float x) { return x > 0.f ? x : 0.2f * x; }

// ---------------- layer-1 aggregation (fp16 gather, single-pass) + h2/e2 epilogue ----------------
__global__ __launch_bounds__(256) void agg1_k(const float* __restrict__ Wmu,
                                              const float* __restrict__ amus,
                                              const float* __restrict__ amud) {
    int warp = (blockIdx.x * blockDim.x + threadIdx.x) >> 5;
    int lane = threadIdx.x & 31;
    if (warp >= N_NODES) return;
    int v = warp;
    int beg = g_off[v], end = g_off[v + 1];
    float h2_0 = 0.f, h2_1 = 0.f;
    if (beg < end) {
        float edv = g_ed1[v];
        float a0 = 0.f, a1 = 0.f, a2 = 0.f, a3 = 0.f, d = 0.f;
        int j = beg;
        for (; j + 4 <= end; j += 4) {
            int s0 = g_csr_src[j];
            int s1 = g_csr_src[j + 1];
            int s2 = g_csr_src[j + 2];
            int s3 = g_csr_src[j + 3];
            float w0 = expf(leaky(g_es1[s0] + edv));
            float w1 = expf(leaky(g_es1[s1] + edv));
            float w2 = expf(leaky(g_es1[s2] + edv));
            float w3 = expf(leaky(g_es1[s3] + edv));
            const uint32_t* hp0 = g_h16 + (size_t)s0 * (F_HID / 2);
            const uint32_t* hp1 = g_h16 + (size_t)s1 * (F_HID / 2);
            const uint32_t* hp2 = g_h16 + (size_t)s2 * (F_HID / 2);
            const uint32_t* hp3 = g_h16 + (size_t)s3 * (F_HID / 2);
            uint32_t p00 = hp0[lane], p01 = hp0[lane + 32];
            uint32_t p10 = hp1[lane], p11 = hp1[lane + 32];
            uint32_t p20 = hp2[lane], p21 = hp2[lane + 32];
            uint32_t p30 = hp3[lane], p31 = hp3[lane + 32];
            float2 x00 = __half22float2(*(__half2*)&p00), x01 = __half22float2(*(__half2*)&p01);
            float2 x10 = __half22float2(*(__half2*)&p10), x11 = __half22float2(*(__half2*)&p11);
            float2 x20 = __half22float2(*(__half2*)&p20), x21 = __half22float2(*(__half2*)&p21);
            float2 x30 = __half22float2(*(__half2*)&p30), x31 = __half22float2(*(__half2*)&p31);
            d += (w0 + w1) + (w2 + w3);
            a0 += w0 * x00.x + w1 * x10.x + w2 * x20.x + w3 * x30.x;
            a1 += w0 * x00.y + w1 * x10.y + w2 * x20.y + w3 * x30.y;
            a2 += w0 * x01.x + w1 * x11.x + w2 * x21.x + w3 * x31.x;
            a3 += w0 * x01.y + w1 * x11.y + w2 * x21.y + w3 * x31.y;
        }
        for (; j < end; j++) {
            int s = g_csr_src[j];
            float wgt = expf(leaky(g_es1[s] + edv));
            const uint32_t* hp = g_h16 + (size_t)s * (F_HID / 2);
            uint32_t p0 = hp[lane], p1 = hp[lane + 32];
            float2 x0 = __half22float2(*(__half2*)&p0), x1 = __half22float2(*(__half2*)&p1);
            d += wgt;
            a0 += wgt * x0.x;
            a1 += wgt * x0.y;
            a2 += wgt * x1.x;
            a3 += wgt * x1.y;
        }
        float inv = 1.f / fmaxf(d, 1e-16f);
        a0 = fmaxf(a0 * inv, 0.f);
        a1 = fmaxf(a1 * inv, 0.f);
        a2 = fmaxf(a2 * inv, 0.f);
        a3 = fmaxf(a3 * inv, 0.f);
        // feature indices: f0=2*lane, f1=2*lane+1, f2=64+2*lane, f3=64+2*lane+1
        int f0 = 2 * lane, f1 = 2 * lane + 1, f2 = 64 + 2 * lane, f3 = 64 + 2 * lane + 1;
        h2_0 = a0 * Wmu[f0 * 2]     + a1 * Wmu[f1 * 2]     + a2 * Wmu[f2 * 2]     + a3 * Wmu[f3 * 2];
        h2_1 = a0 * Wmu[f0 * 2 + 1] + a1 * Wmu[f1 * 2 + 1] + a2 * Wmu[f2 * 2 + 1] + a3 * Wmu[f3 * 2 + 1];
#pragma unroll
        for (int o = 16; o; o >>= 1) {
            h2_0 += __shfl_xor_sync(0xffffffffu, h2_0, o);
            h2_1 += __shfl_xor_sync(0xffffffffu, h2_1, o);
        }
    }
    if (lane == 0) {
        g_h2[2 * v] = h2_0;
        g_h2[2 * v + 1] = h2_1;
        g_es2[v] = h2_0 * amus[0] + h2_1 * amus[1];
        g_ed2[v] = h2_0 * amud[0] + h2_1 * amud[1];
    }
}

// ---------------- layer-2 aggregation + sampled-softmax logits (fused, single-pass) ----------------
__global__ __launch_bounds__(256) void agg2_logits_k(const int* __restrict__ input_y,
                                                     const int* __restrict__ sample_ids,
                                                     const float* __restrict__ ssw,
                                                     const float* __restrict__ ssb,
                                                     float* __restrict__ out,
                                                     float* __restrict__ mu_out) {
    __shared__ float sw0[N_SAMP], sw1[N_SAMP], sb[N_SAMP];
    for (int i = threadIdx.x; i < N_SAMP; i += blockDim.x) {
        int sid = sample_ids[i];
        sw0[i] = ssw[2 * sid];
        sw1[i] = ssw[2 * sid + 1];
        sb[i] = ssb[sid];
    }
    __syncthreads();

    int warp = (blockIdx.x * blockDim.x + threadIdx.x) >> 5;
    int lane = threadIdx.x & 31;
    if (warp >= N_NODES) return;
    int v = warp;
    int beg = g_off[v], end = g_off[v + 1];
    float mu0 = 0.f, mu1 = 0.f;
    if (beg < end) {
        float edv = g_ed2[v];
        float d = 0.f, a0 = 0.f, a1 = 0.f;
        for (int j = beg + lane; j < end; j += 32) {
            int s = g_csr_src[j];
            float wgt = expf(leaky(g_es2[s] + edv));
            float2 hv = *(const float2*)&g_h2[2 * s];
            d += wgt;
            a0 += wgt * hv.x;
            a1 += wgt * hv.y;
        }
#pragma unroll
        for (int o = 16; o; o >>= 1) {
            d  += __shfl_xor_sync(0xffffffffu, d, o);
            a0 += __shfl_xor_sync(0xffffffffu, a0, o);
            a1 += __shfl_xor_sync(0xffffffffu, a1, o);
        }
        float inv = 1.f / fmaxf(d, 1e-16f);
        mu0 = a0 * inv;
        mu1 = a1 * inv;
    }
    float* row = out + (size_t)v * (N_SAMP + 1);
    if (lane == 0) {
        mu_out[2 * v] = mu0;
        mu_out[2 * v + 1] = mu1;
        int y = input_y[v];
        float tl = mu0 * ssw[2 * y] + mu1 * ssw[2 * y + 1] + ssb[y];
        __stcs(&row[0], tl);
    }
    for (int c = lane + 1; c <= N_SAMP; c += 32) {
        int s = c - 1;
        __stcs(&row[c], mu0 * sw0[s] + mu1 * sw1[s] + sb[s]);
    }
}

// ---------------- launch (fork/join: CSR chain overlaps GEMM) ----------------
static cudaStream_t g_s2 = nullptr;
static cudaEvent_t g_ev_fork = nullptr;
static cudaEvent_t g_ev_join = nullptr;

extern "C" void kernel_launch(void* const* d_in, const int* in_sizes, int n_in,
                              void* d_out, int out_size) {
    const float* X         = (const float*)d_in[0];
    const int*   input_y   = (const int*)d_in[2];
    const int*   edge_idx  = (const int*)d_in[3];
    const int*   sample_ids= (const int*)d_in[4];
    const float* W1        = (const float*)d_in[5];
    const float* a1_src    = (const float*)d_in[6];
    const float* a1_dst    = (const float*)d_in[7];
    const float* W_mu      = (const float*)d_in[8];
    const float* amu_src   = (const float*)d_in[9];
    const float* amu_dst   = (const float*)d_in[10];
    const float* ss_weight = (const float*)d_in[14];
    const float* ss_bias   = (const float*)d_in[15];
    float* out = (float*)d_out;

    float* mu_out = out + (size_t)N_NODES * (N_SAMP + 1);

    if (g_s2 == nullptr) {
        cudaStreamCreateWithFlags(&g_s2, cudaStreamNonBlocking);
        cudaEventCreateWithFlags(&g_ev_fork, cudaEventDisableTiming);
        cudaEventCreateWithFlags(&g_ev_join, cudaEventDisableTiming);
    }

    // counts zero + W1 split (needed by both branches)
    zero_split_k<<<(N_NODES + 255) / 256, 256>>>(W1);

    // fork: CSR chain on side stream
    cudaEventRecord(g_ev_fork, 0);
    cudaStreamWaitEvent(g_s2, g_ev_fork, 0);
    hist_k<<<(N_EDGES + 255) / 256, 256, 0, g_s2>>>(edge_idx);
    bsum_k<<<SCAN_NB, SCAN_B, 0, g_s2>>>();
    scan_bsums_k<<<1, 512, 0, g_s2>>>();
    write_off_k<<<SCAN_NB, SCAN_B, 0, g_s2>>>();
    fill_k<<<(N_EDGES + 255) / 256, 256, 0, g_s2>>>(edge_idx);
    cudaEventRecord(g_ev_join, g_s2);

    // main stream: tensor-core GEMM with fused attention-dot epilogue (concurrent)
    gemm_mma_k<<<(N_NODES + 127) / 128, 256>>>(X, a1_src, a1_dst);

    // join, then aggregation phases
    cudaStreamWaitEvent(0, g_ev_join, 0);
    int warp_blocks = (N_NODES * 32 + 255) / 256;
    agg1_k<<<warp_blocks, 256>>>(W_mu, amu_src, amu_dst);
    agg2_logits_k<<<warp_blocks, 256>>>(input_y, sample_ids, ss_weight, ss_bias, out, mu_out);
}

// round 8
// speedup vs baseline: 2.3130x; 1.0296x over previous
#include <cuda_runtime.h>
#include <cuda_bf16.h>
#include <cuda_fp16.h>
#include <math.h>
#include <stdint.h>

#define N_NODES 100000
#define N_EDGES 1600000
#define F_IN 256
#define F_HID 128
#define VOCAB 100000
#define N_SAMP 512

#define SCAN_B 256
#define SCAN_NB ((N_NODES + SCAN_B - 1) / SCAN_B)   // 391

// ---------------- scratch (static __device__ — no allocations) ----------------
__device__ uint32_t g_h16[(size_t)N_NODES * (F_HID / 2)];   // h as half2 pairs, 25.6 MB
__device__ float g_es1[N_NODES];
__device__ float g_ed1[N_NODES];
__device__ int   g_counts[N_NODES];
__device__ int   g_off[N_NODES + 1];
__device__ int   g_cursor[N_NODES];
__device__ int   g_csr_src[N_EDGES];
__device__ float g_h2[2 * N_NODES];
__device__ float g_es2[N_NODES];
__device__ float g_ed2[N_NODES];
__device__ int   g_bsum[SCAN_NB];
__device__ int   g_boff[SCAN_NB];
__device__ __nv_bfloat16 g_Bt_hi[F_HID * F_IN];
__device__ __nv_bfloat16 g_Bt_lo[F_HID * F_IN];
// compact gathered sample tables (filled once per call)
__device__ float g_sw0[N_SAMP];
__device__ float g_sw1[N_SAMP];
__device__ float g_sb[N_SAMP];

// ---------------- prep: zero counts + W1 split + sample-table gather ----------------
__global__ void zero_split_k(const float* __restrict__ W1,
                             const int* __restrict__ sample_ids,
                             const float* __restrict__ ssw,
                             const float* __restrict__ ssb) {
    int i = blockIdx.x * blockDim.x + threadIdx.x;
    if (i < N_NODES) g_counts[i] = 0;
    if (i < F_HID * F_IN) {
        int n = i / F_IN;
        int k = i % F_IN;
        float w = W1[(size_t)k * F_HID + n];
        __nv_bfloat16 hi = __float2bfloat16(w);
        float r = w - __bfloat162float(hi);
        g_Bt_hi[i] = hi;
        g_Bt_lo[i] = __float2bfloat16(r);
    }
    if (i < N_SAMP) {
        int sid = sample_ids[i];
        g_sw0[i] = ssw[2 * sid];
        g_sw1[i] = ssw[2 * sid + 1];
        g_sb[i] = ssb[sid];
    }
}

__global__ void hist_k(const int* __restrict__ edge_index) {
    int e = blockIdx.x * blockDim.x + threadIdx.x;
    if (e < N_EDGES) {
        int dst = edge_index[N_EDGES + e];
        atomicAdd(&g_counts[dst], 1);
    }
}

__global__ __launch_bounds__(SCAN_B) void bsum_k() {
    int i = blockIdx.x * SCAN_B + threadIdx.x;
    int c = (i < N_NODES) ? g_counts[i] : 0;
#pragma unroll
    for (int o = 16; o; o >>= 1) c += __shfl_xor_sync(0xffffffffu, c, o);
    __shared__ int ws[SCAN_B / 32];
    if ((threadIdx.x & 31) == 0) ws[threadIdx.x >> 5] = c;
    __syncthreads();
    if (threadIdx.x < SCAN_B / 32) {
        int v = ws[threadIdx.x];
#pragma unroll
        for (int o = SCAN_B / 64; o; o >>= 1) v += __shfl_xor_sync(0xffffffffu, v, o);
        if (threadIdx.x == 0) g_bsum[blockIdx.x] = v;
    }
}

__global__ __launch_bounds__(512) void scan_bsums_k() {
    __shared__ int s[512];
    int t = threadIdx.x;
    int v = (t < SCAN_NB) ? g_bsum[t] : 0;
    s[t] = v;
    __syncthreads();
    for (int d = 1; d < 512; d <<= 1) {
        int x = 0;
        if (t >= d) x = s[t - d];
        __syncthreads();
        s[t] += x;
        __syncthreads();
    }
    if (t < SCAN_NB) g_boff[t] = s[t] - v;
    if (t == 511) g_off[N_NODES] = s[SCAN_NB - 1];
}

__global__ __launch_bounds__(SCAN_B) void write_off_k() {
    int i = blockIdx.x * SCAN_B + threadIdx.x;
    int lane = threadIdx.x & 31;
    int wid = threadIdx.x >> 5;
    int c = (i < N_NODES) ? g_counts[i] : 0;
    int inc = c;
#pragma unroll
    for (int d = 1; d < 32; d <<= 1) {
        int x = __shfl_up_sync(0xffffffffu, inc, d);
        if (lane >= d) inc += x;
    }
    __shared__ int wsum[SCAN_B / 32];
    if (lane == 31) wsum[wid] = inc;
    __syncthreads();
    if (threadIdx.x == 0) {
        int run = 0;
#pragma unroll
        for (int wv = 0; wv < SCAN_B / 32; wv++) {
            int x = wsum[wv];
            wsum[wv] = run;
            run += x;
        }
    }
    __syncthreads();
    int off = g_boff[blockIdx.x] + wsum[wid] + inc - c;
    if (i < N_NODES) {
        g_off[i] = off;
        g_cursor[i] = off;
    }
}

__global__ void fill_k(const int* __restrict__ edge_index) {
    int e = blockIdx.x * blockDim.x + threadIdx.x;
    if (e < N_EDGES) {
        int src = edge_index[e];
        int dst = edge_index[N_EDGES + e];
        int pos = atomicAdd(&g_cursor[dst], 1);
        g_csr_src[pos] = src;
    }
}

// ---------------- tensor-core GEMM + fused attention-dot epilogue (h -> fp16) ----------------
#define SMEM_STRIDE 40

__device__ __forceinline__ void mma16816(float* d,
                                         uint32_t a0, uint32_t a1, uint32_t a2, uint32_t a3,
                                         uint32_t b0, uint32_t b1) {
    asm volatile(
        "mma.sync.aligned.m16n8k16.row.col.f32.bf16.bf16.f32 "
        "{%0,%1,%2,%3}, {%4,%5,%6,%7}, {%8,%9}, {%0,%1,%2,%3};\n"
        : "+f"(d[0]), "+f"(d[1]), "+f"(d[2]), "+f"(d[3])
        : "r"(a0), "r"(a1), "r"(a2), "r"(a3), "r"(b0), "r"(b1));
}

__global__ __launch_bounds__(256) void gemm_mma_k(const float* __restrict__ A,
                                                  const float* __restrict__ a1_src,
                                                  const float* __restrict__ a1_dst) {
    __shared__ __nv_bfloat16 As_hi[128][SMEM_STRIDE];
    __shared__ __nv_bfloat16 As_lo[128][SMEM_STRIDE];
    __shared__ __nv_bfloat16 Bs_hi[128][SMEM_STRIDE];
    __shared__ __nv_bfloat16 Bs_lo[128][SMEM_STRIDE];
    __shared__ float es_s[128][2], ed_s[128][2];

    const int tid = threadIdx.x;
    const int block_row = blockIdx.x * 128;
    const int w = tid >> 5, l = tid & 31;
    const int warp_m = (w >> 1) * 32;
    const int warp_n = (w & 1) * 64;
    const int nhalf = w & 1;

    float acc[2][8][4];
#pragma unroll
    for (int i = 0; i < 2; i++)
#pragma unroll
        for (int j = 0; j < 8; j++)
#pragma unroll
            for (int q = 0; q < 4; q++) acc[i][j][q] = 0.f;

    const int ar = tid >> 1;
    const int ac = (tid & 1) * 16;

    for (int k0 = 0; k0 < F_IN; k0 += 32) {
        {
            int gr = block_row + ar;
#pragma unroll
            for (int j = 0; j < 4; j++) {
                float4 v = make_float4(0.f, 0.f, 0.f, 0.f);
                if (gr < N_NODES)
                    v = *(const float4*)(A + (size_t)gr * F_IN + k0 + ac + j * 4);
                float xs[4] = {v.x, v.y, v.z, v.w};
                __nv_bfloat16 hi[4], lo[4];
#pragma unroll
                for (int c = 0; c < 4; c++) {
                    hi[c] = __float2bfloat16(xs[c]);
                    lo[c] = __float2bfloat16(xs[c] - __bfloat162float(hi[c]));
                }
                __nv_bfloat162* ph = (__nv_bfloat162*)&As_hi[ar][ac + j * 4];
                __nv_bfloat162* pl = (__nv_bfloat162*)&As_lo[ar][ac + j * 4];
                ph[0] = __nv_bfloat162(hi[0], hi[1]);
                ph[1] = __nv_bfloat162(hi[2], hi[3]);
                pl[0] = __nv_bfloat162(lo[0], lo[1]);
                pl[1] = __nv_bfloat162(lo[2], lo[3]);
            }
        }
        {
            const __nv_bfloat16* bh = g_Bt_hi + (size_t)ar * F_IN + k0 + ac;
            const __nv_bfloat16* bl = g_Bt_lo + (size_t)ar * F_IN + k0 + ac;
            *(uint4*)&Bs_hi[ar][ac] = *(const uint4*)bh;
            *(uint4*)&Bs_hi[ar][ac + 8] = *(const uint4*)(bh + 8);
            *(uint4*)&Bs_lo[ar][ac] = *(const uint4*)bl;
            *(uint4*)&Bs_lo[ar][ac + 8] = *(const uint4*)(bl + 8);
        }
        __syncthreads();

#pragma unroll
        for (int ks = 0; ks < 32; ks += 16) {
            const int fr = l >> 2;
            const int fc = ks + (l & 3) * 2;
            uint32_t ah[2][4], al[2][4];
#pragma unroll
            for (int mf = 0; mf < 2; mf++) {
                int r = warp_m + mf * 16 + fr;
                ah[mf][0] = *(const uint32_t*)&As_hi[r][fc];
                ah[mf][1] = *(const uint32_t*)&As_hi[r + 8][fc];
                ah[mf][2] = *(const uint32_t*)&As_hi[r][fc + 8];
                ah[mf][3] = *(const uint32_t*)&As_hi[r + 8][fc + 8];
                al[mf][0] = *(const uint32_t*)&As_lo[r][fc];
                al[mf][1] = *(const uint32_t*)&As_lo[r + 8][fc];
                al[mf][2] = *(const uint32_t*)&As_lo[r][fc + 8];
                al[mf][3] = *(const uint32_t*)&As_lo[r + 8][fc + 8];
            }
#pragma unroll
            for (int nf = 0; nf < 8; nf++) {
                int n = warp_n + nf * 8 + fr;
                uint32_t bh0 = *(const uint32_t*)&Bs_hi[n][fc];
                uint32_t bh1 = *(const uint32_t*)&Bs_hi[n][fc + 8];
                uint32_t bl0 = *(const uint32_t*)&Bs_lo[n][fc];
                uint32_t bl1 = *(const uint32_t*)&Bs_lo[n][fc + 8];
#pragma unroll
                for (int mf = 0; mf < 2; mf++) {
                    mma16816(acc[mf][nf], ah[mf][0], ah[mf][1], ah[mf][2], ah[mf][3], bh0, bh1);
                    mma16816(acc[mf][nf], ah[mf][0], ah[mf][1], ah[mf][2], ah[mf][3], bl0, bl1);
                    mma16816(acc[mf][nf], al[mf][0], al[mf][1], al[mf][2], al[mf][3], bh0, bh1);
                }
            }
        }
        __syncthreads();
    }

    const int fr = l >> 2;
    const int quad = l & 3;

#pragma unroll
    for (int mf = 0; mf < 2; mf++) {
        int rl0 = warp_m + mf * 16 + fr;
        int rl1 = rl0 + 8;
        int r0 = block_row + rl0;
        int r1 = block_row + rl1;
        float es0 = 0.f, ed0 = 0.f, es1 = 0.f, ed1 = 0.f;
#pragma unroll
        for (int nf = 0; nf < 8; nf++) {
            int cc = warp_n + nf * 8 + quad * 2;
            float as0 = a1_src[cc], as1 = a1_src[cc + 1];
            float ad0 = a1_dst[cc], ad1 = a1_dst[cc + 1];
            es0 += acc[mf][nf][0] * as0 + acc[mf][nf][1] * as1;
            ed0 += acc[mf][nf][0] * ad0 + acc[mf][nf][1] * ad1;
            es1 += acc[mf][nf][2] * as0 + acc[mf][nf][3] * as1;
            ed1 += acc[mf][nf][2] * ad0 + acc[mf][nf][3] * ad1;
            if (r0 < N_NODES) {
                __half2 hv = __floats2half2_rn(acc[mf][nf][0], acc[mf][nf][1]);
                g_h16[(size_t)r0 * (F_HID / 2) + (cc >> 1)] = *(uint32_t*)&hv;
            }
            if (r1 < N_NODES) {
                __half2 hv = __floats2half2_rn(acc[mf][nf][2], acc[mf][nf][3]);
                g_h16[(size_t)r1 * (F_HID / 2) + (cc >> 1)] = *(uint32_t*)&hv;
            }
        }
#pragma unroll
        for (int o = 1; o <= 2; o <<= 1) {
            es0 += __shfl_xor_sync(0xffffffffu, es0, o);
            ed0 += __shfl_xor_sync(0xffffffffu, ed0, o);
            es1 += __shfl_xor_sync(0xffffffffu, es1, o);
            ed1 += __shfl_xor_sync(0xffffffffu, ed1, o);
        }
        if (quad == 0) {
            es_s[rl0][nhalf] = es0;
            ed_s[rl0][nhalf] = ed0;
            es_s[rl1][nhalf] = es1;
            ed_s[rl1][nhalf] = ed1;
        }
    }
    __syncthreads();
    if (tid < 128) {
        int gr = block_row + tid;
        if (gr < N_NODES) {
            g_es1[gr] = es_s[tid][0] + es_s[tid][1];
            g_ed1[gr] = ed_s[tid][0] + ed_s[tid][1];
        }
    }
}

__device__ __forceinline__ float leaky(float x) { return x > 0.f ? x : 0.2f * x; }

// ---------------- layer-1 aggregation (fp16 gather, single-pass) + h2/e2 epilogue ----------------
__global__ __launch_bounds__(256) void agg1_k(const float* __restrict__ Wmu,
                                              const float* __restrict__ amus,
                                              const float* __restrict__ amud) {
    int warp = (blockIdx.x * blockDim.x + threadIdx.x) >> 5;
    int lane = threadIdx.x & 31;
    if (warp >= N_NODES) return;
    int v = warp;
    int beg = g_off[v], end = g_off[v + 1];
    float h2_0 = 0.f, h2_1 = 0.f;
    if (beg < end) {
        float edv = g_ed1[v];
        float a0 = 0.f, a1 = 0.f, a2 = 0.f, a3 = 0.f, d = 0.f;
        int j = beg;
        for (; j + 4 <= end; j += 4) {
            int s0 = g_csr_src[j];
            int s1 = g_csr_src[j + 1];
            int s2 = g_csr_src[j + 2];
            int s3 = g_csr_src[j + 3];
            float w0 = expf(leaky(g_es1[s0] + edv));
            float w1 = expf(leaky(g_es1[s1] + edv));
            float w2 = expf(leaky(g_es1[s2] + edv));
            float w3 = expf(leaky(g_es1[s3] + edv));
            const uint32_t* hp0 = g_h16 + (size_t)s0 * (F_HID / 2);
            const uint32_t* hp1 = g_h16 + (size_t)s1 * (F_HID / 2);
            const uint32_t* hp2 = g_h16 + (size_t)s2 * (F_HID / 2);
            const uint32_t* hp3 = g_h16 + (size_t)s3 * (F_HID / 2);
            uint32_t p00 = hp0[lane], p01 = hp0[lane + 32];
            uint32_t p10 = hp1[lane], p11 = hp1[lane + 32];
            uint32_t p20 = hp2[lane], p21 = hp2[lane + 32];
            uint32_t p30 = hp3[lane], p31 = hp3[lane + 32];
            float2 x00 = __half22float2(*(__half2*)&p00), x01 = __half22float2(*(__half2*)&p01);
            float2 x10 = __half22float2(*(__half2*)&p10), x11 = __half22float2(*(__half2*)&p11);
            float2 x20 = __half22float2(*(__half2*)&p20), x21 = __half22float2(*(__half2*)&p21);
            float2 x30 = __half22float2(*(__half2*)&p30), x31 = __half22float2(*(__half2*)&p31);
            d += (w0 + w1) + (w2 + w3);
            a0 += w0 * x00.x + w1 * x10.x + w2 * x20.x + w3 * x30.x;
            a1 += w0 * x00.y + w1 * x10.y + w2 * x20.y + w3 * x30.y;
            a2 += w0 * x01.x + w1 * x11.x + w2 * x21.x + w3 * x31.x;
            a3 += w0 * x01.y + w1 * x11.y + w2 * x21.y + w3 * x31.y;
        }
        for (; j < end; j++) {
            int s = g_csr_src[j];
            float wgt = expf(leaky(g_es1[s] + edv));
            const uint32_t* hp = g_h16 + (size_t)s * (F_HID / 2);
            uint32_t p0 = hp[lane], p1 = hp[lane + 32];
            float2 x0 = __half22float2(*(__half2*)&p0), x1 = __half22float2(*(__half2*)&p1);
            d += wgt;
            a0 += wgt * x0.x;
            a1 += wgt * x0.y;
            a2 += wgt * x1.x;
            a3 += wgt * x1.y;
        }
        float inv = 1.f / fmaxf(d, 1e-16f);
        a0 = fmaxf(a0 * inv, 0.f);
        a1 = fmaxf(a1 * inv, 0.f);
        a2 = fmaxf(a2 * inv, 0.f);
        a3 = fmaxf(a3 * inv, 0.f);
        int f0 = 2 * lane, f1 = 2 * lane + 1, f2 = 64 + 2 * lane, f3 = 64 + 2 * lane + 1;
        h2_0 = a0 * Wmu[f0 * 2]     + a1 * Wmu[f1 * 2]     + a2 * Wmu[f2 * 2]     + a3 * Wmu[f3 * 2];
        h2_1 = a0 * Wmu[f0 * 2 + 1] + a1 * Wmu[f1 * 2 + 1] + a2 * Wmu[f2 * 2 + 1] + a3 * Wmu[f3 * 2 + 1];
#pragma unroll
        for (int o = 16; o; o >>= 1) {
            h2_0 += __shfl_xor_sync(0xffffffffu, h2_0, o);
            h2_1 += __shfl_xor_sync(0xffffffffu, h2_1, o);
        }
    }
    if (lane == 0) {
        g_h2[2 * v] = h2_0;
        g_h2[2 * v + 1] = h2_1;
        g_es2[v] = h2_0 * amus[0] + h2_1 * amus[1];
        g_ed2[v] = h2_0 * amud[0] + h2_1 * amud[1];
    }
}

// ---------------- layer-2 aggregation + sampled-softmax logits (fused, single-pass) ----------------
__global__ __launch_bounds__(256) void agg2_logits_k(const int* __restrict__ input_y,
                                                     const float* __restrict__ ssw,
                                                     const float* __restrict__ ssb,
                                                     float* __restrict__ out,
                                                     float* __restrict__ mu_out) {
    __shared__ float sw0[N_SAMP], sw1[N_SAMP], sb[N_SAMP];
    // coalesced fill from compact precomputed tables (float4)
    for (int i = threadIdx.x; i < N_SAMP / 4; i += blockDim.x) {
        *(float4*)&sw0[i * 4] = *(const float4*)&g_sw0[i * 4];
        *(float4*)&sw1[i * 4] = *(const float4*)&g_sw1[i * 4];
        *(float4*)&sb[i * 4]  = *(const float4*)&g_sb[i * 4];
    }
    __syncthreads();

    int warp = (blockIdx.x * blockDim.x + threadIdx.x) >> 5;
    int lane = threadIdx.x & 31;
    if (warp >= N_NODES) return;
    int v = warp;
    int beg = g_off[v], end = g_off[v + 1];
    float mu0 = 0.f, mu1 = 0.f;
    if (beg < end) {
        float edv = g_ed2[v];
        float d = 0.f, a0 = 0.f, a1 = 0.f;
        for (int j = beg + lane; j < end; j += 32) {
            int s = g_csr_src[j];
            float wgt = expf(leaky(g_es2[s] + edv));
            float2 hv = *(const float2*)&g_h2[2 * s];
            d += wgt;
            a0 += wgt * hv.x;
            a1 += wgt * hv.y;
        }
#pragma unroll
        for (int o = 16; o; o >>= 1) {
            d  += __shfl_xor_sync(0xffffffffu, d, o);
            a0 += __shfl_xor_sync(0xffffffffu, a0, o);
            a1 += __shfl_xor_sync(0xffffffffu, a1, o);
        }
        float inv = 1.f / fmaxf(d, 1e-16f);
        mu0 = a0 * inv;
        mu1 = a1 * inv;
    }
    float* row = out + (size_t)v * (N_SAMP + 1);
    if (lane == 0) {
        mu_out[2 * v] = mu0;
        mu_out[2 * v + 1] = mu1;
        int y = input_y[v];
        float tl = mu0 * ssw[2 * y] + mu1 * ssw[2 * y + 1] + ssb[y];
        __stcs(&row[0], tl);
    }
    for (int c = lane + 1; c <= N_SAMP; c += 32) {
        int s = c - 1;
        __stcs(&row[c], mu0 * sw0[s] + mu1 * sw1[s] + sb[s]);
    }
}

// ---------------- launch (fork/join: CSR chain overlaps GEMM) ----------------
static cudaStream_t g_s2 = nullptr;
static cudaEvent_t g_ev_fork = nullptr;
static cudaEvent_t g_ev_join = nullptr;

extern "C" void kernel_launch(void* const* d_in, const int* in_sizes, int n_in,
                              void* d_out, int out_size) {
    const float* X         = (const float*)d_in[0];
    const int*   input_y   = (const int*)d_in[2];
    const int*   edge_idx  = (const int*)d_in[3];
    const int*   sample_ids= (const int*)d_in[4];
    const float* W1        = (const float*)d_in[5];
    const float* a1_src    = (const float*)d_in[6];
    const float* a1_dst    = (const float*)d_in[7];
    const float* W_mu      = (const float*)d_in[8];
    const float* amu_src   = (const float*)d_in[9];
    const float* amu_dst   = (const float*)d_in[10];
    const float* ss_weight = (const float*)d_in[14];
    const float* ss_bias   = (const float*)d_in[15];
    float* out = (float*)d_out;

    float* mu_out = out + (size_t)N_NODES * (N_SAMP + 1);

    if (g_s2 == nullptr) {
        cudaStreamCreateWithFlags(&g_s2, cudaStreamNonBlocking);
        cudaEventCreateWithFlags(&g_ev_fork, cudaEventDisableTiming);
        cudaEventCreateWithFlags(&g_ev_join, cudaEventDisableTiming);
    }

    // prep: counts zero + W1 split + sample table gather
    zero_split_k<<<(N_NODES + 255) / 256, 256>>>(W1, sample_ids, ss_weight, ss_bias);

    // fork: CSR chain on side stream
    cudaEventRecord(g_ev_fork, 0);
    cudaStreamWaitEvent(g_s2, g_ev_fork, 0);
    hist_k<<<(N_EDGES + 255) / 256, 256, 0, g_s2>>>(edge_idx);
    bsum_k<<<SCAN_NB, SCAN_B, 0, g_s2>>>();
    scan_bsums_k<<<1, 512, 0, g_s2>>>();
    write_off_k<<<SCAN_NB, SCAN_B, 0, g_s2>>>();
    fill_k<<<(N_EDGES + 255) / 256, 256, 0, g_s2>>>(edge_idx);
    cudaEventRecord(g_ev_join, g_s2);

    // main stream: tensor-core GEMM with fused attention-dot epilogue (concurrent)
    gemm_mma_k<<<(N_NODES + 127) / 128, 256>>>(X, a1_src, a1_dst);

    // join, then aggregation phases
    cudaStreamWaitEvent(0, g_ev_join, 0);
    int warp_blocks = (N_NODES * 32 + 255) / 256;
    agg1_k<<<warp_blocks, 256>>>(W_mu, amu_src, amu_dst);
    agg2_logits_k<<<warp_blocks, 256>>>(input_y, ss_weight, ss_bias, out, mu_out);
}